// round 14
// baseline (speedup 1.0000x reference)
#include <cuda_runtime.h>
#include <cuda_bf16.h>
#include <cstdint>
#include <math.h>

typedef __nv_bfloat16 bf16;

#define Bb   2
#define Tt   2048
#define DM   2048
#define Hh   16
#define Dd   128
#define HALF 64

// ---------------------------------------------------------------------------
// Device scratch (static — no runtime allocation allowed)
// ---------------------------------------------------------------------------
__device__ float g_q[(size_t)Bb * Hh * Tt * Dd];     // fp32 [b][h][t][d] (pre-rope)
__device__ float g_k[(size_t)Bb * Hh * Tt * Dd];
__device__ float g_v[(size_t)Bb * Hh * Tt * Dd];

// split-bf16 attention operands [b][h][t][d]
__device__ bf16 g_qh[(size_t)Bb * Hh * Tt * Dd], g_ql[(size_t)Bb * Hh * Tt * Dd];
__device__ bf16 g_kh[(size_t)Bb * Hh * Tt * Dd], g_kl[(size_t)Bb * Hh * Tt * Dd];
__device__ bf16 g_vh[(size_t)Bb * Hh * Tt * Dd], g_vl[(size_t)Bb * Hh * Tt * Dd];

// split-bf16 GEMM operands
__device__ bf16 g_xh[(size_t)Bb * Tt * DM];
__device__ bf16 g_xl[(size_t)Bb * Tt * DM];
__device__ bf16 g_cxh[(size_t)Bb * Tt * DM];   // ctx splits, written by attention
__device__ bf16 g_cxl[(size_t)Bb * Tt * DM];
__device__ bf16 g_wqh[(size_t)DM * DM], g_wql[(size_t)DM * DM];
__device__ bf16 g_wkh[(size_t)DM * DM], g_wkl[(size_t)DM * DM];
__device__ bf16 g_wvh[(size_t)DM * DM], g_wvl[(size_t)DM * DM];
__device__ bf16 g_woh[(size_t)DM * DM], g_wol[(size_t)DM * DM];

// ---------------------------------------------------------------------------
// PTX helpers (sm_80-class only — bench ptxas target is plain sm_103)
// ---------------------------------------------------------------------------
__device__ __forceinline__ uint32_t smem_u32(const void* p) {
    uint32_t a;
    asm("{ .reg .u64 t; cvta.to.shared.u64 t, %1; cvt.u32.u64 %0, t; }"
        : "=r"(a) : "l"(p));
    return a;
}
__device__ __forceinline__ void cp16(uint32_t dst, const void* src) {
    asm volatile("cp.async.cg.shared.global [%0], [%1], 16;" :: "r"(dst), "l"(src));
}
#define CP_COMMIT()   asm volatile("cp.async.commit_group;" ::: "memory")
#define CP_WAIT(n)    asm volatile("cp.async.wait_group %0;" :: "n"(n) : "memory")

__device__ __forceinline__ void ldsm4(uint32_t* r, uint32_t a) {
    asm volatile("ldmatrix.sync.aligned.m8n8.x4.shared.b16 {%0,%1,%2,%3}, [%4];"
                 : "=r"(r[0]), "=r"(r[1]), "=r"(r[2]), "=r"(r[3]) : "r"(a));
}
__device__ __forceinline__ void ldsm4t(uint32_t* r, uint32_t a) {
    asm volatile("ldmatrix.sync.aligned.m8n8.x4.trans.shared.b16 {%0,%1,%2,%3}, [%4];"
                 : "=r"(r[0]), "=r"(r[1]), "=r"(r[2]), "=r"(r[3]) : "r"(a));
}
__device__ __forceinline__ void ldsm2(uint32_t* r, uint32_t a) {
    asm volatile("ldmatrix.sync.aligned.m8n8.x2.shared.b16 {%0,%1}, [%2];"
                 : "=r"(r[0]), "=r"(r[1]) : "r"(a));
}
__device__ __forceinline__ void mma16816(float* c, const uint32_t* a, const uint32_t* b) {
    asm volatile(
        "mma.sync.aligned.m16n8k16.row.col.f32.bf16.bf16.f32 "
        "{%0,%1,%2,%3}, {%4,%5,%6,%7}, {%8,%9}, {%0,%1,%2,%3};"
        : "+f"(c[0]), "+f"(c[1]), "+f"(c[2]), "+f"(c[3])
        : "r"(a[0]), "r"(a[1]), "r"(a[2]), "r"(a[3]), "r"(b[0]), "r"(b[1]));
}
__device__ __forceinline__ uint32_t pack_bf2(float a, float b) {
    __nv_bfloat162 h = __floats2bfloat162_rn(a, b);
    return *(uint32_t*)&h;
}
__device__ __forceinline__ void split_store(bf16* hi, bf16* lo, size_t i, float v) {
    bf16 h = __float2bfloat16(v);
    hi[i] = h;
    lo[i] = __float2bfloat16(v - __bfloat162float(h));
}

// ---------------------------------------------------------------------------
// mma.sync split-bf16 GEMM: C[4096 x 2048] = A[4096,2048] * W[2048,2048]^T
// CTA 128(M) x 256(N), 256 threads (8 warps = 2x4), warp tile 64x64.
// BK=32, 3-stage cp.async pipeline; stage = [Ah 8K][Al 8K][Bh 16K][Bl 16K]
// = 48KB, 3 stages = 144KB smem. Single sync per chunk, 2-chunk lookahead
// (round-8 pipeline structure, proven).
// Rows are 64B (32 bf16) = 4 x 16B chunks; swizzle chunk ^= (row>>1)&3
// (round-3-proven conflict-free ldmatrix mapping).
// LDSM:MMA ratio = 0.25 (half of the round-8 64x32 tile).
// ---------------------------------------------------------------------------
#define NSTAGE 3
#define STAGE_BYTES 49152
#define GEMM_SMEM (NSTAGE * STAGE_BYTES)
#define NK (DM / 32)

__device__ __forceinline__ uint32_t sw32(int row, int chunk) {
    return (uint32_t)(row * 64 + ((chunk ^ ((row >> 1) & 3)) * 16));
}

__device__ __forceinline__ void load_stage(uint32_t sbuf,
    const bf16* __restrict__ Ah, const bf16* __restrict__ Al,
    const bf16* __restrict__ Bh, const bf16* __restrict__ Bl,
    int m0, int n0, int k0, int tid)
{
    #pragma unroll
    for (int i = 0; i < 12; ++i) {
        int idx = tid + i * 256;              // 0..3071
        if (idx < 1024) {                     // A: 128 rows x 4 chunks x 2 splits
            int half = idx >> 9;              // 0=Ah 1=Al
            int rem  = idx & 511;
            int r = rem >> 2, c = rem & 3;
            const bf16* src = half ? Al : Ah;
            cp16(sbuf + half * 8192 + sw32(r, c),
                 (const char*)src + ((size_t)(m0 + r) * DM + k0 + c * 8) * 2);
        } else {                              // B: 256 rows x 4 chunks x 2 splits
            int j = idx - 1024;               // 0..2047
            int half = j >> 10;               // 0=Bh 1=Bl
            int rem  = j & 1023;
            int r = rem >> 2, c = rem & 3;    // row 0..255
            const bf16* src = half ? Bl : Bh;
            cp16(sbuf + 16384 + half * 16384 + sw32(r, c),
                 (const char*)src + ((size_t)(n0 + r) * DM + k0 + c * 8) * 2);
        }
    }
}

__device__ __forceinline__ void compute_stage(uint32_t sbuf,
    float acc[4][8][4], int wm, int wn, int lane)
{
    const int arow = lane & 15;
    const int achk = lane >> 4;          // 0 or 1
    const int brow = lane & 7;
    const int bchk = (lane >> 3) & 1;
    #pragma unroll
    for (int ks = 0; ks < 2; ++ks) {
        uint32_t ah[4][4], al[4][4], bh[8][2], bl[8][2];
        #pragma unroll
        for (int mt = 0; mt < 4; ++mt) {
            int r = wm * 64 + mt * 16 + arow;
            uint32_t ad = sbuf + sw32(r, ks * 2 + achk);
            ldsm4(ah[mt], ad);
            ldsm4(al[mt], ad + 8192);
        }
        #pragma unroll
        for (int nt = 0; nt < 8; ++nt) {
            int r = wn * 64 + nt * 8 + brow;
            uint32_t bd = sbuf + 16384 + sw32(r, ks * 2 + bchk);
            ldsm2(bh[nt], bd);
            ldsm2(bl[nt], bd + 16384);
        }
        // term-major: all 32 accs visited before any acc repeats
        #pragma unroll
        for (int mt = 0; mt < 4; ++mt)
            #pragma unroll
            for (int nt = 0; nt < 8; ++nt)
                mma16816(acc[mt][nt], ah[mt], bh[nt]);
        #pragma unroll
        for (int mt = 0; mt < 4; ++mt)
            #pragma unroll
            for (int nt = 0; nt < 8; ++nt)
                mma16816(acc[mt][nt], ah[mt], bl[nt]);
        #pragma unroll
        for (int mt = 0; mt < 4; ++mt)
            #pragma unroll
            for (int nt = 0; nt < 8; ++nt)
                mma16816(acc[mt][nt], al[mt], bh[nt]);
    }
}

template<bool QKV>
__global__ void __launch_bounds__(256, 1) gemm_tc(
    const bf16* __restrict__ Ah,  const bf16* __restrict__ Al,
    const bf16* __restrict__ Bh0, const bf16* __restrict__ Bl0,
    const bf16* __restrict__ Bh1, const bf16* __restrict__ Bl1,
    const bf16* __restrict__ Bh2, const bf16* __restrict__ Bl2,
    float* __restrict__ outp)
{
    extern __shared__ char smp[];
    const int tid  = threadIdx.x;
    const int wid  = tid >> 5;
    const int lane = tid & 31;
    const int wm   = wid >> 2;    // 0..1  (M, 64 rows each)
    const int wn   = wid & 3;     // 0..3  (N, 64 cols each)
    const int m0 = blockIdx.y * 128;
    const int n0 = blockIdx.x * 256;

    const bf16* Bh = Bh0;
    const bf16* Bl = Bl0;
    float* out = outp;
    if (QKV) {
        if (blockIdx.z == 1)      { Bh = Bh1; Bl = Bl1; out = g_k; }
        else if (blockIdx.z == 2) { Bh = Bh2; Bl = Bl2; out = g_v; }
        else                      { out = g_q; }
    }

    const uint32_t sbase = smem_u32(smp);

    float acc[4][8][4];
    #pragma unroll
    for (int a = 0; a < 4; ++a)
        #pragma unroll
        for (int b = 0; b < 8; ++b)
            #pragma unroll
            for (int c = 0; c < 4; ++c) acc[a][b][c] = 0.0f;

    // prologue: fill 2 stages
    load_stage(sbase, Ah, Al, Bh, Bl, m0, n0, 0, tid);
    CP_COMMIT();
    load_stage(sbase + STAGE_BYTES, Ah, Al, Bh, Bl, m0, n0, 32, tid);
    CP_COMMIT();

    uint32_t bufs[3] = {sbase, sbase + STAGE_BYTES, sbase + 2 * STAGE_BYTES};
    for (int kt = 0; kt < NK; ++kt) {
        CP_WAIT(1);
        __syncthreads();
        if (kt + 2 < NK) {
            load_stage(bufs[(kt + 2) % 3], Ah, Al, Bh, Bl, m0, n0, (kt + 2) * 32, tid);
            CP_COMMIT();
        }
        compute_stage(bufs[kt % 3], acc, wm, wn, lane);
    }

    const int lr = lane >> 2;
    const int lc = (lane & 3) * 2;
    #pragma unroll
    for (int mt = 0; mt < 4; ++mt) {
        #pragma unroll
        for (int nt = 0; nt < 8; ++nt) {
            int mA = m0 + wm * 64 + mt * 16 + lr;
            int col = n0 + wn * 64 + nt * 8 + lc;
            float2 v0 = make_float2(acc[mt][nt][0], acc[mt][nt][1]);
            float2 v1 = make_float2(acc[mt][nt][2], acc[mt][nt][3]);
            if (QKV) {
                const int h = col >> 7, d = col & 127;
                int b = mA >> 11, t = mA & (Tt - 1);
                *(float2*)(out + (((size_t)b * Hh + h) * Tt + t) * Dd + d) = v0;
                int mB = mA + 8;
                b = mB >> 11; t = mB & (Tt - 1);
                *(float2*)(out + (((size_t)b * Hh + h) * Tt + t) * Dd + d) = v1;
            } else {
                *(float2*)(out + (size_t)mA * DM + col) = v0;
                *(float2*)(out + (size_t)(mA + 8) * DM + col) = v1;
            }
        }
    }
}

// ---------------------------------------------------------------------------
// fp32 -> (hi, lo) bf16 split — single launch for x (2 halves) + 4 weights
// ---------------------------------------------------------------------------
#define CONV_Z_ELEMS (DM * DM)   // 4M elements per z-slice
__global__ void convert_all(
    const float4* __restrict__ x,
    const float4* __restrict__ wq, const float4* __restrict__ wk,
    const float4* __restrict__ wv, const float4* __restrict__ wo,
    __nv_bfloat162* __restrict__ xh, __nv_bfloat162* __restrict__ xl,
    __nv_bfloat162* __restrict__ wqh, __nv_bfloat162* __restrict__ wql,
    __nv_bfloat162* __restrict__ wkh, __nv_bfloat162* __restrict__ wkl,
    __nv_bfloat162* __restrict__ wvh, __nv_bfloat162* __restrict__ wvl,
    __nv_bfloat162* __restrict__ woh, __nv_bfloat162* __restrict__ wol)
{
    const int z = blockIdx.z;
    const int q4 = CONV_Z_ELEMS / 4;  // float4s per z-slice
    const float4* src;
    __nv_bfloat162 *hi, *lo;
    switch (z) {
        case 0: src = x;           hi = xh;            lo = xl;            break;
        case 1: src = x + q4;      hi = xh + q4 * 2;   lo = xl + q4 * 2;   break;
        case 2: src = wq;          hi = wqh;           lo = wql;           break;
        case 3: src = wk;          hi = wkh;           lo = wkl;           break;
        case 4: src = wv;          hi = wvh;           lo = wvl;           break;
        default: src = wo;         hi = woh;           lo = wol;           break;
    }
    int i = blockIdx.x * blockDim.x + threadIdx.x;
    if (i >= q4) return;
    float4 f = src[i];
    bf16 h0 = __float2bfloat16(f.x), h1 = __float2bfloat16(f.y);
    bf16 h2 = __float2bfloat16(f.z), h3 = __float2bfloat16(f.w);
    hi[2 * i]     = __halves2bfloat162(h0, h1);
    hi[2 * i + 1] = __halves2bfloat162(h2, h3);
    *(uint32_t*)&lo[2 * i]     = pack_bf2(f.x - __bfloat162float(h0), f.y - __bfloat162float(h1));
    *(uint32_t*)&lo[2 * i + 1] = pack_bf2(f.z - __bfloat162float(h2), f.w - __bfloat162float(h3));
}

// ---------------------------------------------------------------------------
// RoPE + split to bf16 (q gets 1/sqrt(D) folded in)
// ---------------------------------------------------------------------------
__global__ void rope_split(const float* __restrict__ cos_t,
                           const float* __restrict__ sin_t, float qscale)
{
    int idx = blockIdx.x * blockDim.x + threadIdx.x;
    if (idx >= Bb * Hh * Tt * HALF) return;
    int dp  = idx & (HALF - 1);
    int row = idx >> 6;
    int t   = row & (Tt - 1);
    float c = cos_t[t * HALF + dp];
    float s = sin_t[t * HALF + dp];
    size_t base = (size_t)row * Dd;

    float q1 = g_q[base + dp], q2 = g_q[base + dp + HALF];
    split_store(g_qh, g_ql, base + dp,        (q1 * c - q2 * s) * qscale);
    split_store(g_qh, g_ql, base + dp + HALF, (q1 * s + q2 * c) * qscale);

    float k1 = g_k[base + dp], k2 = g_k[base + dp + HALF];
    split_store(g_kh, g_kl, base + dp,        k1 * c - k2 * s);
    split_store(g_kh, g_kl, base + dp + HALF, k1 * s + k2 * c);

    float v1 = g_v[base + dp], v2 = g_v[base + dp + HALF];
    split_store(g_vh, g_vl, base + dp,        v1);
    split_store(g_vh, g_vl, base + dp + HALF, v2);
}

// ---------------------------------------------------------------------------
// Flash attention on mma.sync, split-bf16, causal (proven; unchanged).
// BQ=128 q-rows/CTA (8 warps x 16 rows), BKT=64 KV per step.
// SMEM: [Qh 32K][Ql 32K] + 2 stages x [Kh 16K][Kl 16K][Vh 16K][Vl 16K] = 192K.
// ---------------------------------------------------------------------------
#define ATTN2_SMEM 196608

__device__ __forceinline__ uint32_t aoff(int row, int chunk) {
    return (uint32_t)(row * 256 + ((chunk ^ (row & 7)) * 16));
}

__device__ __forceinline__ void attn_load_stage(uint32_t sb, int bhT, int k0, int tid)
{
    #pragma unroll
    for (int t8 = 0; t8 < 16; ++t8) {
        int i = tid + t8 * 256;
        int tile = i >> 10;
        int rem = i & 1023;
        int row = rem >> 4, chunk = rem & 15;
        const bf16* src = (tile == 0) ? g_kh : (tile == 1) ? g_kl
                        : (tile == 2) ? g_vh : g_vl;
        cp16(sb + tile * 16384 + aoff(row, chunk),
             src + (((size_t)(bhT + k0 + row)) << 7) + chunk * 8);
    }
}

__global__ void __launch_bounds__(256, 1) attn_mma()
{
    extern __shared__ char smp[];
    const uint32_t sb = smem_u32(smp);
    const int tid  = threadIdx.x;
    const int wid  = tid >> 5;
    const int lane = tid & 31;
    const int bh   = blockIdx.y;
    const int qi   = gridDim.x - 1 - blockIdx.x;   // heavy tiles first
    const int q0   = qi * 128;
    const int bhT  = bh * Tt;
    const int wrow = wid * 16;

    // Load Q tile (qh, ql): 128 rows x 256B each
    #pragma unroll
    for (int t8 = 0; t8 < 16; ++t8) {
        int i = tid + t8 * 256;
        int tile = i >> 11;
        int rem = i & 2047;
        int row = rem >> 4, chunk = rem & 15;
        const bf16* src = tile ? g_ql : g_qh;
        cp16(sb + tile * 32768 + aoff(row, chunk),
             src + (((size_t)(bhT + q0 + row)) << 7) + chunk * 8);
    }
    attn_load_stage(sb + 65536, bhT, 0, tid);
    CP_COMMIT();

    float m1 = -1e30f, m2 = -1e30f, l1 = 0.0f, l2 = 0.0f;
    float O[16][4];
    #pragma unroll
    for (int i = 0; i < 16; ++i)
        #pragma unroll
        for (int j = 0; j < 4; ++j) O[i][j] = 0.0f;

    const int nsteps = 2 * qi + 2;
    for (int s = 0; s < nsteps; ++s) {
        if (s + 1 < nsteps) {
            attn_load_stage(sb + 65536 + ((s + 1) & 1) * 65536, bhT, (s + 1) * 64, tid);
            CP_COMMIT();
            CP_WAIT(1);
        } else {
            CP_WAIT(0);
        }
        __syncthreads();
        const uint32_t stg = sb + 65536 + (s & 1) * 65536;

        // ---- S = Q K^T (3-term split, fp32 acc, pre-scaled) ----
        float sa[8][4];
        #pragma unroll
        for (int i = 0; i < 8; ++i)
            #pragma unroll
            for (int j = 0; j < 4; ++j) sa[i][j] = 0.0f;

        const int arow = wrow + (lane & 15);
        #pragma unroll
        for (int ks = 0; ks < 8; ++ks) {
            uint32_t ah[4], al[4];
            uint32_t ad = sb + aoff(arow, ks * 2 + (lane >> 4));
            ldsm4(ah, ad);
            ldsm4(al, ad + 32768);
            #pragma unroll
            for (int ntp = 0; ntp < 4; ++ntp) {
                int brow = ntp * 16 + (lane & 7) + (lane >> 4) * 8;
                int bchk = ks * 2 + ((lane >> 3) & 1);
                uint32_t kbh[4], kbl[4];
                uint32_t bd = stg + aoff(brow, bchk);
                ldsm4(kbh, bd);
                ldsm4(kbl, bd + 16384);
                mma16816(sa[2 * ntp],     ah, kbh);
                mma16816(sa[2 * ntp + 1], ah, kbh + 2);
                mma16816(sa[2 * ntp],     ah, kbl);
                mma16816(sa[2 * ntp + 1], ah, kbl + 2);
                mma16816(sa[2 * ntp],     al, kbh);
                mma16816(sa[2 * ntp + 1], al, kbh + 2);
            }
        }

        // ---- causal mask (diagonal steps only) ----
        const int k0 = s * 64;
        const int gr1 = q0 + wrow + (lane >> 2);
        const int gr2 = gr1 + 8;
        if (s >= 2 * qi) {
            #pragma unroll
            for (int nt = 0; nt < 8; ++nt) {
                int c = k0 + nt * 8 + (lane & 3) * 2;
                if (c     > gr1) sa[nt][0] = -1e30f;
                if (c + 1 > gr1) sa[nt][1] = -1e30f;
                if (c     > gr2) sa[nt][2] = -1e30f;
                if (c + 1 > gr2) sa[nt][3] = -1e30f;
            }
        }

        // ---- online softmax (rows fully intra-warp) ----
        float mx1 = -1e30f, mx2 = -1e30f;
        #pragma unroll
        for (int nt = 0; nt < 8; ++nt) {
            mx1 = fmaxf(mx1, fmaxf(sa[nt][0], sa[nt][1]));
            mx2 = fmaxf(mx2, fmaxf(sa[nt][2], sa[nt][3]));
        }
        mx1 = fmaxf(mx1, __shfl_xor_sync(0xffffffff, mx1, 1));
        mx1 = fmaxf(mx1, __shfl_xor_sync(0xffffffff, mx1, 2));
        mx2 = fmaxf(mx2, __shfl_xor_sync(0xffffffff, mx2, 1));
        mx2 = fmaxf(mx2, __shfl_xor_sync(0xffffffff, mx2, 2));
        float mn1 = fmaxf(m1, mx1), mn2 = fmaxf(m2, mx2);
        float al1 = __expf(m1 - mn1), al2 = __expf(m2 - mn2);
        m1 = mn1; m2 = mn2;

        float rs1 = 0.0f, rs2 = 0.0f;
        uint32_t pa_h[8], pa_l[8], pb_h[8], pb_l[8];
        #pragma unroll
        for (int nt = 0; nt < 8; ++nt) {
            float p0 = __expf(sa[nt][0] - mn1);
            float p1 = __expf(sa[nt][1] - mn1);
            float p2 = __expf(sa[nt][2] - mn2);
            float p3 = __expf(sa[nt][3] - mn2);
            rs1 += p0 + p1;
            rs2 += p2 + p3;
            bf16 h0 = __float2bfloat16(p0), h1 = __float2bfloat16(p1);
            bf16 h2 = __float2bfloat16(p2), h3 = __float2bfloat16(p3);
            pa_h[nt] = ((uint32_t)*(uint16_t*)&h1 << 16) | *(uint16_t*)&h0;
            pb_h[nt] = ((uint32_t)*(uint16_t*)&h3 << 16) | *(uint16_t*)&h2;
            pa_l[nt] = pack_bf2(p0 - __bfloat162float(h0), p1 - __bfloat162float(h1));
            pb_l[nt] = pack_bf2(p2 - __bfloat162float(h2), p3 - __bfloat162float(h3));
        }
        rs1 += __shfl_xor_sync(0xffffffff, rs1, 1);
        rs1 += __shfl_xor_sync(0xffffffff, rs1, 2);
        rs2 += __shfl_xor_sync(0xffffffff, rs2, 1);
        rs2 += __shfl_xor_sync(0xffffffff, rs2, 2);
        l1 = l1 * al1 + rs1;
        l2 = l2 * al2 + rs2;

        #pragma unroll
        for (int nt = 0; nt < 16; ++nt) {
            O[nt][0] *= al1; O[nt][1] *= al1;
            O[nt][2] *= al2; O[nt][3] *= al2;
        }

        // ---- O += P V (3-term split; V via ldmatrix.trans) ----
        #pragma unroll
        for (int kt = 0; kt < 4; ++kt) {
            uint32_t A_h[4] = {pa_h[2 * kt], pb_h[2 * kt], pa_h[2 * kt + 1], pb_h[2 * kt + 1]};
            uint32_t A_l[4] = {pa_l[2 * kt], pb_l[2 * kt], pa_l[2 * kt + 1], pb_l[2 * kt + 1]};
            int vrow = kt * 16 + (lane & 7) + ((lane >> 3) & 1) * 8;
            #pragma unroll
            for (int g = 0; g < 8; ++g) {
                int vchk = g * 2 + (lane >> 4);
                uint32_t vbh[4], vbl[4];
                uint32_t vd = stg + 32768 + aoff(vrow, vchk);
                ldsm4t(vbh, vd);
                ldsm4t(vbl, vd + 16384);
                mma16816(O[2 * g],     A_h, vbh);
                mma16816(O[2 * g + 1], A_h, vbh + 2);
                mma16816(O[2 * g],     A_h, vbl);
                mma16816(O[2 * g + 1], A_h, vbl + 2);
                mma16816(O[2 * g],     A_l, vbh);
                mma16816(O[2 * g + 1], A_l, vbh + 2);
            }
        }
        __syncthreads();
    }

    // ---- epilogue: normalize, split to bf16, write ctx splits ----
    const float inv1 = 1.0f / l1, inv2 = 1.0f / l2;
    const int b = bh >> 4, h = bh & 15;
    const int r1 = q0 + wrow + (lane >> 2);
    #pragma unroll
    for (int nt = 0; nt < 16; ++nt) {
        int col = h * Dd + nt * 8 + (lane & 3) * 2;
        size_t i1 = ((size_t)(b * Tt + r1)) * DM + col;
        size_t i2 = i1 + 8 * DM;
        float o0 = O[nt][0] * inv1, o1 = O[nt][1] * inv1;
        float o2 = O[nt][2] * inv2, o3 = O[nt][3] * inv2;
        bf16 h0 = __float2bfloat16(o0), h1 = __float2bfloat16(o1);
        bf16 h2 = __float2bfloat16(o2), h3 = __float2bfloat16(o3);
        *(uint32_t*)(g_cxh + i1) = ((uint32_t)*(uint16_t*)&h1 << 16) | *(uint16_t*)&h0;
        *(uint32_t*)(g_cxh + i2) = ((uint32_t)*(uint16_t*)&h3 << 16) | *(uint16_t*)&h2;
        *(uint32_t*)(g_cxl + i1) = pack_bf2(o0 - __bfloat162float(h0), o1 - __bfloat162float(h1));
        *(uint32_t*)(g_cxl + i2) = pack_bf2(o2 - __bfloat162float(h2), o3 - __bfloat162float(h3));
    }
}

// ---------------------------------------------------------------------------
extern "C" void kernel_launch(void* const* d_in, const int* in_sizes, int n_in,
                              void* d_out, int out_size)
{
    const float* x  = (const float*)d_in[0];
    const float* wq = (const float*)d_in[1];
    const float* wk = (const float*)d_in[2];
    const float* wv = (const float*)d_in[3];
    const float* wo = (const float*)d_in[4];
    const float* cs = (const float*)d_in[5];
    const float* sn = (const float*)d_in[6];
    float* out = (float*)d_out;

    bf16 *xh, *xl, *cxh, *cxl, *wqh, *wql, *wkh, *wkl, *wvh, *wvl, *woh, *wol;
    cudaGetSymbolAddress((void**)&xh,  g_xh);  cudaGetSymbolAddress((void**)&xl,  g_xl);
    cudaGetSymbolAddress((void**)&cxh, g_cxh); cudaGetSymbolAddress((void**)&cxl, g_cxl);
    cudaGetSymbolAddress((void**)&wqh, g_wqh); cudaGetSymbolAddress((void**)&wql, g_wql);
    cudaGetSymbolAddress((void**)&wkh, g_wkh); cudaGetSymbolAddress((void**)&wkl, g_wkl);
    cudaGetSymbolAddress((void**)&wvh, g_wvh); cudaGetSymbolAddress((void**)&wvl, g_wvl);
    cudaGetSymbolAddress((void**)&woh, g_woh); cudaGetSymbolAddress((void**)&wol, g_wol);

    // 1. one fused split-conversion launch (x as 2 z-slices + 4 weights)
    const int q4 = CONV_Z_ELEMS / 4;   // 1M float4 per z-slice
    convert_all<<<dim3((q4 + 255) / 256, 1, 6), 256>>>(
        (const float4*)x, (const float4*)wq, (const float4*)wk,
        (const float4*)wv, (const float4*)wo,
        (__nv_bfloat162*)xh, (__nv_bfloat162*)xl,
        (__nv_bfloat162*)wqh, (__nv_bfloat162*)wql,
        (__nv_bfloat162*)wkh, (__nv_bfloat162*)wkl,
        (__nv_bfloat162*)wvh, (__nv_bfloat162*)wvl,
        (__nv_bfloat162*)woh, (__nv_bfloat162*)wol);

    // 2. QKV projection (mma.sync, 128x256 CTA / 64x64 warp tiles, 3-stage BK=32)
    cudaFuncSetAttribute(gemm_tc<true>,  cudaFuncAttributeMaxDynamicSharedMemorySize, GEMM_SMEM);
    cudaFuncSetAttribute(gemm_tc<false>, cudaFuncAttributeMaxDynamicSharedMemorySize, GEMM_SMEM);
    gemm_tc<true><<<dim3(DM / 256, (Bb * Tt) / 128, 3), 256, GEMM_SMEM>>>(
        xh, xl, wqh, wql, wkh, wkl, wvh, wvl, nullptr);

    // 3. RoPE + split to bf16 (q scaled by 1/sqrt(D))
    int nrope = Bb * Hh * Tt * HALF;
    rope_split<<<(nrope + 255) / 256, 256>>>(cs, sn, 1.0f / sqrtf((float)Dd));

    // 4. Flash attention (mma.sync) -> writes ctx splits directly
    cudaFuncSetAttribute(attn_mma, cudaFuncAttributeMaxDynamicSharedMemorySize, ATTN2_SMEM);
    attn_mma<<<dim3(Tt / 128, Bb * Hh), 256, ATTN2_SMEM>>>();

    // 5. output projection -> d_out
    gemm_tc<false><<<dim3(DM / 256, (Bb * Tt) / 128, 1), 256, GEMM_SMEM>>>(
        cxh, cxl, woh, wol, woh, wol, woh, wol, out);
}

// round 15
// speedup vs baseline: 1.1046x; 1.1046x over previous
#include <cuda_runtime.h>
#include <cuda_bf16.h>
#include <cstdint>
#include <math.h>

typedef __nv_bfloat16 bf16;

#define Bb   2
#define Tt   2048
#define DM   2048
#define Hh   16
#define Dd   128
#define HALF 64

// ---------------------------------------------------------------------------
// Device scratch (static — no runtime allocation allowed)
// ---------------------------------------------------------------------------
__device__ float g_q[(size_t)Bb * Hh * Tt * Dd];     // fp32 [b][h][t][d] (pre-rope)
__device__ float g_k[(size_t)Bb * Hh * Tt * Dd];
__device__ float g_v[(size_t)Bb * Hh * Tt * Dd];

// split-bf16 attention operands [b][h][t][d]
__device__ bf16 g_qh[(size_t)Bb * Hh * Tt * Dd], g_ql[(size_t)Bb * Hh * Tt * Dd];
__device__ bf16 g_kh[(size_t)Bb * Hh * Tt * Dd], g_kl[(size_t)Bb * Hh * Tt * Dd];
__device__ bf16 g_vh[(size_t)Bb * Hh * Tt * Dd], g_vl[(size_t)Bb * Hh * Tt * Dd];

// split-bf16 GEMM operands
__device__ bf16 g_xh[(size_t)Bb * Tt * DM];
__device__ bf16 g_xl[(size_t)Bb * Tt * DM];
__device__ bf16 g_cxh[(size_t)Bb * Tt * DM];   // ctx splits, written by attention
__device__ bf16 g_cxl[(size_t)Bb * Tt * DM];
__device__ bf16 g_wqh[(size_t)DM * DM], g_wql[(size_t)DM * DM];
__device__ bf16 g_wkh[(size_t)DM * DM], g_wkl[(size_t)DM * DM];
__device__ bf16 g_wvh[(size_t)DM * DM], g_wvl[(size_t)DM * DM];
__device__ bf16 g_woh[(size_t)DM * DM], g_wol[(size_t)DM * DM];

// ---------------------------------------------------------------------------
// PTX helpers (sm_80-class only — bench ptxas target is plain sm_103)
// ---------------------------------------------------------------------------
__device__ __forceinline__ uint32_t smem_u32(const void* p) {
    uint32_t a;
    asm("{ .reg .u64 t; cvta.to.shared.u64 t, %1; cvt.u32.u64 %0, t; }"
        : "=r"(a) : "l"(p));
    return a;
}
__device__ __forceinline__ void cp16(uint32_t dst, const void* src) {
    asm volatile("cp.async.cg.shared.global [%0], [%1], 16;" :: "r"(dst), "l"(src));
}
#define CP_COMMIT()   asm volatile("cp.async.commit_group;" ::: "memory")
#define CP_WAIT(n)    asm volatile("cp.async.wait_group %0;" :: "n"(n) : "memory")

__device__ __forceinline__ void ldsm4(uint32_t* r, uint32_t a) {
    asm volatile("ldmatrix.sync.aligned.m8n8.x4.shared.b16 {%0,%1,%2,%3}, [%4];"
                 : "=r"(r[0]), "=r"(r[1]), "=r"(r[2]), "=r"(r[3]) : "r"(a));
}
__device__ __forceinline__ void ldsm4t(uint32_t* r, uint32_t a) {
    asm volatile("ldmatrix.sync.aligned.m8n8.x4.trans.shared.b16 {%0,%1,%2,%3}, [%4];"
                 : "=r"(r[0]), "=r"(r[1]), "=r"(r[2]), "=r"(r[3]) : "r"(a));
}
__device__ __forceinline__ void ldsm2(uint32_t* r, uint32_t a) {
    asm volatile("ldmatrix.sync.aligned.m8n8.x2.shared.b16 {%0,%1}, [%2];"
                 : "=r"(r[0]), "=r"(r[1]) : "r"(a));
}
__device__ __forceinline__ void mma16816(float* c, const uint32_t* a, const uint32_t* b) {
    asm volatile(
        "mma.sync.aligned.m16n8k16.row.col.f32.bf16.bf16.f32 "
        "{%0,%1,%2,%3}, {%4,%5,%6,%7}, {%8,%9}, {%0,%1,%2,%3};"
        : "+f"(c[0]), "+f"(c[1]), "+f"(c[2]), "+f"(c[3])
        : "r"(a[0]), "r"(a[1]), "r"(a[2]), "r"(a[3]), "r"(b[0]), "r"(b[1]));
}
__device__ __forceinline__ uint32_t pack_bf2(float a, float b) {
    __nv_bfloat162 h = __floats2bfloat162_rn(a, b);
    return *(uint32_t*)&h;
}

// ---------------------------------------------------------------------------
// mma.sync split-bf16 GEMM (round-8 proven configuration, byte-identical):
// CTA 128x128, 256 threads, 64x32 warp tile, BK=64, 3-stage pipeline (192KB).
// Stage: [Ah 16K][Al 16K][Bh 16K][Bl 16K]. Rows 128B = 8 chunks, chunk ^= row&7.
// B via ldsm2; term-major MMA order.
// ---------------------------------------------------------------------------
#define NSTAGE 3
#define STAGE_BYTES 65536
#define GEMM_SMEM (NSTAGE * STAGE_BYTES)
#define NK (DM / 64)

__device__ __forceinline__ uint32_t sw_off(int row, int chunk) {
    return (uint32_t)(row * 128 + ((chunk ^ (row & 7)) * 16));
}

__device__ __forceinline__ void load_stage(uint32_t sbuf,
    const bf16* __restrict__ Ah, const bf16* __restrict__ Al,
    const bf16* __restrict__ Bh, const bf16* __restrict__ Bl,
    int m0, int n0, int k0, int tid)
{
    #pragma unroll
    for (int i = 0; i < 16; ++i) {
        int idx = tid + i * 256;          // 0..4095
        int tile = idx >> 10;             // 0..3  (Ah, Al, Bh, Bl)
        int rem  = idx & 1023;
        int r = rem >> 3, c = rem & 7;    // row 0..127, chunk 0..7
        uint32_t so = sw_off(r, c);
        const bf16* src = (tile == 0) ? Ah : (tile == 1) ? Al
                        : (tile == 2) ? Bh : Bl;
        int rg = (tile < 2) ? (m0 + r) : (n0 + r);
        cp16(sbuf + tile * 16384 + so,
             (const char*)src + ((size_t)rg * DM + k0 + c * 8) * 2);
    }
}

__device__ __forceinline__ void compute_stage(uint32_t sbuf,
    float acc[4][4][4], int wm, int wn, int lane)
{
    const int arow = lane & 15;
    const int achk = lane >> 4;          // 0 or 1
    const int brow = lane & 7;
    const int bchk = (lane >> 3) & 1;
    #pragma unroll
    for (int ks = 0; ks < 4; ++ks) {
        uint32_t ah[4][4], al[4][4], bh[4][2], bl[4][2];
        #pragma unroll
        for (int mt = 0; mt < 4; ++mt) {
            int r = wm * 64 + mt * 16 + arow;
            uint32_t ad = sbuf + sw_off(r, ks * 2 + achk);
            ldsm4(ah[mt], ad);
            ldsm4(al[mt], ad + 16384);
        }
        #pragma unroll
        for (int nt = 0; nt < 4; ++nt) {
            int r = wn * 32 + nt * 8 + brow;
            uint32_t bd = sbuf + 32768 + sw_off(r, ks * 2 + bchk);
            ldsm2(bh[nt], bd);
            ldsm2(bl[nt], bd + 16384);
        }
        // term-major: all 16 accs visited before any acc repeats
        #pragma unroll
        for (int mt = 0; mt < 4; ++mt)
            #pragma unroll
            for (int nt = 0; nt < 4; ++nt)
                mma16816(acc[mt][nt], ah[mt], bh[nt]);
        #pragma unroll
        for (int mt = 0; mt < 4; ++mt)
            #pragma unroll
            for (int nt = 0; nt < 4; ++nt)
                mma16816(acc[mt][nt], ah[mt], bl[nt]);
        #pragma unroll
        for (int mt = 0; mt < 4; ++mt)
            #pragma unroll
            for (int nt = 0; nt < 4; ++nt)
                mma16816(acc[mt][nt], al[mt], bh[nt]);
    }
}

template<bool QKV>
__global__ void __launch_bounds__(256, 1) gemm_tc(
    const bf16* __restrict__ Ah,  const bf16* __restrict__ Al,
    const bf16* __restrict__ Bh0, const bf16* __restrict__ Bl0,
    const bf16* __restrict__ Bh1, const bf16* __restrict__ Bl1,
    const bf16* __restrict__ Bh2, const bf16* __restrict__ Bl2,
    float* __restrict__ outp)
{
    extern __shared__ char smp[];
    const int tid  = threadIdx.x;
    const int wid  = tid >> 5;
    const int lane = tid & 31;
    const int wm   = wid >> 2;
    const int wn   = wid & 3;
    const int m0 = blockIdx.y * 128;
    const int n0 = blockIdx.x * 128;

    const bf16* Bh = Bh0;
    const bf16* Bl = Bl0;
    float* out = outp;
    if (QKV) {
        if (blockIdx.z == 1)      { Bh = Bh1; Bl = Bl1; out = g_k; }
        else if (blockIdx.z == 2) { Bh = Bh2; Bl = Bl2; out = g_v; }
        else                      { out = g_q; }
    }

    const uint32_t sbase = smem_u32(smp);

    float acc[4][4][4];
    #pragma unroll
    for (int a = 0; a < 4; ++a)
        #pragma unroll
        for (int b = 0; b < 4; ++b)
            #pragma unroll
            for (int c = 0; c < 4; ++c) acc[a][b][c] = 0.0f;

    // prologue: fill 2 stages
    load_stage(sbase, Ah, Al, Bh, Bl, m0, n0, 0, tid);
    CP_COMMIT();
    load_stage(sbase + STAGE_BYTES, Ah, Al, Bh, Bl, m0, n0, 64, tid);
    CP_COMMIT();

    uint32_t bufs[3] = {sbase, sbase + STAGE_BYTES, sbase + 2 * STAGE_BYTES};
    for (int kt = 0; kt < NK; ++kt) {
        CP_WAIT(1);
        __syncthreads();
        if (kt + 2 < NK) {
            load_stage(bufs[(kt + 2) % 3], Ah, Al, Bh, Bl, m0, n0, (kt + 2) * 64, tid);
            CP_COMMIT();
        }
        compute_stage(bufs[kt % 3], acc, wm, wn, lane);
    }

    const int lr = lane >> 2;
    const int lc = (lane & 3) * 2;
    #pragma unroll
    for (int mt = 0; mt < 4; ++mt) {
        #pragma unroll
        for (int nt = 0; nt < 4; ++nt) {
            int mA = m0 + wm * 64 + mt * 16 + lr;
            int col = n0 + wn * 32 + nt * 8 + lc;
            float2 v0 = make_float2(acc[mt][nt][0], acc[mt][nt][1]);
            float2 v1 = make_float2(acc[mt][nt][2], acc[mt][nt][3]);
            if (QKV) {
                const int h = col >> 7, d = col & 127;
                int b = mA >> 11, t = mA & (Tt - 1);
                *(float2*)(out + (((size_t)b * Hh + h) * Tt + t) * Dd + d) = v0;
                int mB = mA + 8;
                b = mB >> 11; t = mB & (Tt - 1);
                *(float2*)(out + (((size_t)b * Hh + h) * Tt + t) * Dd + d) = v1;
            } else {
                *(float2*)(out + (size_t)mA * DM + col) = v0;
                *(float2*)(out + (size_t)(mA + 8) * DM + col) = v1;
            }
        }
    }
}

// ---------------------------------------------------------------------------
// fp32 -> (hi, lo) bf16 split — single launch for x (2 halves) + 4 weights
// ---------------------------------------------------------------------------
#define CONV_Z_ELEMS (DM * DM)   // 4M elements per z-slice
__global__ void convert_all(
    const float4* __restrict__ x,
    const float4* __restrict__ wq, const float4* __restrict__ wk,
    const float4* __restrict__ wv, const float4* __restrict__ wo,
    __nv_bfloat162* __restrict__ xh, __nv_bfloat162* __restrict__ xl,
    __nv_bfloat162* __restrict__ wqh, __nv_bfloat162* __restrict__ wql,
    __nv_bfloat162* __restrict__ wkh, __nv_bfloat162* __restrict__ wkl,
    __nv_bfloat162* __restrict__ wvh, __nv_bfloat162* __restrict__ wvl,
    __nv_bfloat162* __restrict__ woh, __nv_bfloat162* __restrict__ wol)
{
    const int z = blockIdx.z;
    const int q4 = CONV_Z_ELEMS / 4;  // float4s per z-slice
    const float4* src;
    __nv_bfloat162 *hi, *lo;
    switch (z) {
        case 0: src = x;           hi = xh;            lo = xl;            break;
        case 1: src = x + q4;      hi = xh + q4 * 2;   lo = xl + q4 * 2;   break;
        case 2: src = wq;          hi = wqh;           lo = wql;           break;
        case 3: src = wk;          hi = wkh;           lo = wkl;           break;
        case 4: src = wv;          hi = wvh;           lo = wvl;           break;
        default: src = wo;         hi = woh;           lo = wol;           break;
    }
    int i = blockIdx.x * blockDim.x + threadIdx.x;
    if (i >= q4) return;
    float4 f = src[i];
    bf16 h0 = __float2bfloat16(f.x), h1 = __float2bfloat16(f.y);
    bf16 h2 = __float2bfloat16(f.z), h3 = __float2bfloat16(f.w);
    hi[2 * i]     = __halves2bfloat162(h0, h1);
    hi[2 * i + 1] = __halves2bfloat162(h2, h3);
    *(uint32_t*)&lo[2 * i]     = pack_bf2(f.x - __bfloat162float(h0), f.y - __bfloat162float(h1));
    *(uint32_t*)&lo[2 * i + 1] = pack_bf2(f.z - __bfloat162float(h2), f.w - __bfloat162float(h3));
}

// ---------------------------------------------------------------------------
// RoPE + split to bf16, vectorized: one thread handles 4 consecutive dp.
// float4 loads (q, k, v, cos, sin), packed uint32 stores to hi/lo arrays.
// q gets 1/sqrt(D) folded in. Same per-element arithmetic as before.
// ---------------------------------------------------------------------------
__global__ void rope_split(const float* __restrict__ cos_t,
                           const float* __restrict__ sin_t, float qscale)
{
    int idx = blockIdx.x * blockDim.x + threadIdx.x;   // 0 .. B*H*T*16 - 1
    if (idx >= Bb * Hh * Tt * (HALF / 4)) return;
    int dp4 = (idx & 15) * 4;          // 0,4,...,60
    int row = idx >> 4;                // (b*H + h)*T + t
    int t   = row & (Tt - 1);
    size_t base = (size_t)row * Dd;

    float4 c4 = *(const float4*)(cos_t + t * HALF + dp4);
    float4 s4 = *(const float4*)(sin_t + t * HALF + dp4);
    float4 q1 = *(const float4*)(g_q + base + dp4);
    float4 q2 = *(const float4*)(g_q + base + dp4 + HALF);
    float4 k1 = *(const float4*)(g_k + base + dp4);
    float4 k2 = *(const float4*)(g_k + base + dp4 + HALF);
    float4 v1 = *(const float4*)(g_v + base + dp4);
    float4 v2 = *(const float4*)(g_v + base + dp4 + HALF);

    float qo1[4] = {(q1.x * c4.x - q2.x * s4.x) * qscale,
                    (q1.y * c4.y - q2.y * s4.y) * qscale,
                    (q1.z * c4.z - q2.z * s4.z) * qscale,
                    (q1.w * c4.w - q2.w * s4.w) * qscale};
    float qo2[4] = {(q1.x * s4.x + q2.x * c4.x) * qscale,
                    (q1.y * s4.y + q2.y * c4.y) * qscale,
                    (q1.z * s4.z + q2.z * c4.z) * qscale,
                    (q1.w * s4.w + q2.w * c4.w) * qscale};
    float ko1[4] = {k1.x * c4.x - k2.x * s4.x, k1.y * c4.y - k2.y * s4.y,
                    k1.z * c4.z - k2.z * s4.z, k1.w * c4.w - k2.w * s4.w};
    float ko2[4] = {k1.x * s4.x + k2.x * c4.x, k1.y * s4.y + k2.y * c4.y,
                    k1.z * s4.z + k2.z * c4.z, k1.w * s4.w + k2.w * c4.w};
    float vo1[4] = {v1.x, v1.y, v1.z, v1.w};
    float vo2[4] = {v2.x, v2.y, v2.z, v2.w};

    // split + packed stores: 2x uint32 per (array, half)
    #pragma unroll
    for (int g = 0; g < 2; ++g) {
        float* qsel = g ? qo2 : qo1;
        float* ksel = g ? ko2 : ko1;
        float* vsel = g ? vo2 : vo1;
        size_t off = base + dp4 + g * HALF;
        #pragma unroll
        for (int p = 0; p < 2; ++p) {
            float a = qsel[2 * p], b = qsel[2 * p + 1];
            bf16 ha = __float2bfloat16(a), hb = __float2bfloat16(b);
            *(uint32_t*)(g_qh + off + 2 * p) = ((uint32_t)*(uint16_t*)&hb << 16) | *(uint16_t*)&ha;
            *(uint32_t*)(g_ql + off + 2 * p) = pack_bf2(a - __bfloat162float(ha), b - __bfloat162float(hb));

            a = ksel[2 * p]; b = ksel[2 * p + 1];
            ha = __float2bfloat16(a); hb = __float2bfloat16(b);
            *(uint32_t*)(g_kh + off + 2 * p) = ((uint32_t)*(uint16_t*)&hb << 16) | *(uint16_t*)&ha;
            *(uint32_t*)(g_kl + off + 2 * p) = pack_bf2(a - __bfloat162float(ha), b - __bfloat162float(hb));

            a = vsel[2 * p]; b = vsel[2 * p + 1];
            ha = __float2bfloat16(a); hb = __float2bfloat16(b);
            *(uint32_t*)(g_vh + off + 2 * p) = ((uint32_t)*(uint16_t*)&hb << 16) | *(uint16_t*)&ha;
            *(uint32_t*)(g_vl + off + 2 * p) = pack_bf2(a - __bfloat162float(ha), b - __bfloat162float(hb));
        }
    }
}

// ---------------------------------------------------------------------------
// Flash attention on mma.sync, split-bf16, causal (proven; unchanged).
// BQ=128 q-rows/CTA (8 warps x 16 rows), BKT=64 KV per step.
// SMEM: [Qh 32K][Ql 32K] + 2 stages x [Kh 16K][Kl 16K][Vh 16K][Vl 16K] = 192K.
// ---------------------------------------------------------------------------
#define ATTN2_SMEM 196608

__device__ __forceinline__ uint32_t aoff(int row, int chunk) {
    return (uint32_t)(row * 256 + ((chunk ^ (row & 7)) * 16));
}

__device__ __forceinline__ void attn_load_stage(uint32_t sb, int bhT, int k0, int tid)
{
    #pragma unroll
    for (int t8 = 0; t8 < 16; ++t8) {
        int i = tid + t8 * 256;
        int tile = i >> 10;
        int rem = i & 1023;
        int row = rem >> 4, chunk = rem & 15;
        const bf16* src = (tile == 0) ? g_kh : (tile == 1) ? g_kl
                        : (tile == 2) ? g_vh : g_vl;
        cp16(sb + tile * 16384 + aoff(row, chunk),
             src + (((size_t)(bhT + k0 + row)) << 7) + chunk * 8);
    }
}

__global__ void __launch_bounds__(256, 1) attn_mma()
{
    extern __shared__ char smp[];
    const uint32_t sb = smem_u32(smp);
    const int tid  = threadIdx.x;
    const int wid  = tid >> 5;
    const int lane = tid & 31;
    const int bh   = blockIdx.y;
    const int qi   = gridDim.x - 1 - blockIdx.x;   // heavy tiles first
    const int q0   = qi * 128;
    const int bhT  = bh * Tt;
    const int wrow = wid * 16;

    // Load Q tile (qh, ql): 128 rows x 256B each
    #pragma unroll
    for (int t8 = 0; t8 < 16; ++t8) {
        int i = tid + t8 * 256;
        int tile = i >> 11;
        int rem = i & 2047;
        int row = rem >> 4, chunk = rem & 15;
        const bf16* src = tile ? g_ql : g_qh;
        cp16(sb + tile * 32768 + aoff(row, chunk),
             src + (((size_t)(bhT + q0 + row)) << 7) + chunk * 8);
    }
    attn_load_stage(sb + 65536, bhT, 0, tid);
    CP_COMMIT();

    float m1 = -1e30f, m2 = -1e30f, l1 = 0.0f, l2 = 0.0f;
    float O[16][4];
    #pragma unroll
    for (int i = 0; i < 16; ++i)
        #pragma unroll
        for (int j = 0; j < 4; ++j) O[i][j] = 0.0f;

    const int nsteps = 2 * qi + 2;
    for (int s = 0; s < nsteps; ++s) {
        if (s + 1 < nsteps) {
            attn_load_stage(sb + 65536 + ((s + 1) & 1) * 65536, bhT, (s + 1) * 64, tid);
            CP_COMMIT();
            CP_WAIT(1);
        } else {
            CP_WAIT(0);
        }
        __syncthreads();
        const uint32_t stg = sb + 65536 + (s & 1) * 65536;

        // ---- S = Q K^T (3-term split, fp32 acc, pre-scaled) ----
        float sa[8][4];
        #pragma unroll
        for (int i = 0; i < 8; ++i)
            #pragma unroll
            for (int j = 0; j < 4; ++j) sa[i][j] = 0.0f;

        const int arow = wrow + (lane & 15);
        #pragma unroll
        for (int ks = 0; ks < 8; ++ks) {
            uint32_t ah[4], al[4];
            uint32_t ad = sb + aoff(arow, ks * 2 + (lane >> 4));
            ldsm4(ah, ad);
            ldsm4(al, ad + 32768);
            #pragma unroll
            for (int ntp = 0; ntp < 4; ++ntp) {
                int brow = ntp * 16 + (lane & 7) + (lane >> 4) * 8;
                int bchk = ks * 2 + ((lane >> 3) & 1);
                uint32_t kbh[4], kbl[4];
                uint32_t bd = stg + aoff(brow, bchk);
                ldsm4(kbh, bd);
                ldsm4(kbl, bd + 16384);
                mma16816(sa[2 * ntp],     ah, kbh);
                mma16816(sa[2 * ntp + 1], ah, kbh + 2);
                mma16816(sa[2 * ntp],     ah, kbl);
                mma16816(sa[2 * ntp + 1], ah, kbl + 2);
                mma16816(sa[2 * ntp],     al, kbh);
                mma16816(sa[2 * ntp + 1], al, kbh + 2);
            }
        }

        // ---- causal mask (diagonal steps only) ----
        const int k0 = s * 64;
        const int gr1 = q0 + wrow + (lane >> 2);
        const int gr2 = gr1 + 8;
        if (s >= 2 * qi) {
            #pragma unroll
            for (int nt = 0; nt < 8; ++nt) {
                int c = k0 + nt * 8 + (lane & 3) * 2;
                if (c     > gr1) sa[nt][0] = -1e30f;
                if (c + 1 > gr1) sa[nt][1] = -1e30f;
                if (c     > gr2) sa[nt][2] = -1e30f;
                if (c + 1 > gr2) sa[nt][3] = -1e30f;
            }
        }

        // ---- online softmax (rows fully intra-warp) ----
        float mx1 = -1e30f, mx2 = -1e30f;
        #pragma unroll
        for (int nt = 0; nt < 8; ++nt) {
            mx1 = fmaxf(mx1, fmaxf(sa[nt][0], sa[nt][1]));
            mx2 = fmaxf(mx2, fmaxf(sa[nt][2], sa[nt][3]));
        }
        mx1 = fmaxf(mx1, __shfl_xor_sync(0xffffffff, mx1, 1));
        mx1 = fmaxf(mx1, __shfl_xor_sync(0xffffffff, mx1, 2));
        mx2 = fmaxf(mx2, __shfl_xor_sync(0xffffffff, mx2, 1));
        mx2 = fmaxf(mx2, __shfl_xor_sync(0xffffffff, mx2, 2));
        float mn1 = fmaxf(m1, mx1), mn2 = fmaxf(m2, mx2);
        float al1 = __expf(m1 - mn1), al2 = __expf(m2 - mn2);
        m1 = mn1; m2 = mn2;

        float rs1 = 0.0f, rs2 = 0.0f;
        uint32_t pa_h[8], pa_l[8], pb_h[8], pb_l[8];
        #pragma unroll
        for (int nt = 0; nt < 8; ++nt) {
            float p0 = __expf(sa[nt][0] - mn1);
            float p1 = __expf(sa[nt][1] - mn1);
            float p2 = __expf(sa[nt][2] - mn2);
            float p3 = __expf(sa[nt][3] - mn2);
            rs1 += p0 + p1;
            rs2 += p2 + p3;
            bf16 h0 = __float2bfloat16(p0), h1 = __float2bfloat16(p1);
            bf16 h2 = __float2bfloat16(p2), h3 = __float2bfloat16(p3);
            pa_h[nt] = ((uint32_t)*(uint16_t*)&h1 << 16) | *(uint16_t*)&h0;
            pb_h[nt] = ((uint32_t)*(uint16_t*)&h3 << 16) | *(uint16_t*)&h2;
            pa_l[nt] = pack_bf2(p0 - __bfloat162float(h0), p1 - __bfloat162float(h1));
            pb_l[nt] = pack_bf2(p2 - __bfloat162float(h2), p3 - __bfloat162float(h3));
        }
        rs1 += __shfl_xor_sync(0xffffffff, rs1, 1);
        rs1 += __shfl_xor_sync(0xffffffff, rs1, 2);
        rs2 += __shfl_xor_sync(0xffffffff, rs2, 1);
        rs2 += __shfl_xor_sync(0xffffffff, rs2, 2);
        l1 = l1 * al1 + rs1;
        l2 = l2 * al2 + rs2;

        #pragma unroll
        for (int nt = 0; nt < 16; ++nt) {
            O[nt][0] *= al1; O[nt][1] *= al1;
            O[nt][2] *= al2; O[nt][3] *= al2;
        }

        // ---- O += P V (3-term split; V via ldmatrix.trans) ----
        #pragma unroll
        for (int kt = 0; kt < 4; ++kt) {
            uint32_t A_h[4] = {pa_h[2 * kt], pb_h[2 * kt], pa_h[2 * kt + 1], pb_h[2 * kt + 1]};
            uint32_t A_l[4] = {pa_l[2 * kt], pb_l[2 * kt], pa_l[2 * kt + 1], pb_l[2 * kt + 1]};
            int vrow = kt * 16 + (lane & 7) + ((lane >> 3) & 1) * 8;
            #pragma unroll
            for (int g = 0; g < 8; ++g) {
                int vchk = g * 2 + (lane >> 4);
                uint32_t vbh[4], vbl[4];
                uint32_t vd = stg + 32768 + aoff(vrow, vchk);
                ldsm4t(vbh, vd);
                ldsm4t(vbl, vd + 16384);
                mma16816(O[2 * g],     A_h, vbh);
                mma16816(O[2 * g + 1], A_h, vbh + 2);
                mma16816(O[2 * g],     A_h, vbl);
                mma16816(O[2 * g + 1], A_h, vbl + 2);
                mma16816(O[2 * g],     A_l, vbh);
                mma16816(O[2 * g + 1], A_l, vbh + 2);
            }
        }
        __syncthreads();
    }

    // ---- epilogue: normalize, split to bf16, write ctx splits ----
    const float inv1 = 1.0f / l1, inv2 = 1.0f / l2;
    const int b = bh >> 4, h = bh & 15;
    const int r1 = q0 + wrow + (lane >> 2);
    #pragma unroll
    for (int nt = 0; nt < 16; ++nt) {
        int col = h * Dd + nt * 8 + (lane & 3) * 2;
        size_t i1 = ((size_t)(b * Tt + r1)) * DM + col;
        size_t i2 = i1 + 8 * DM;
        float o0 = O[nt][0] * inv1, o1 = O[nt][1] * inv1;
        float o2 = O[nt][2] * inv2, o3 = O[nt][3] * inv2;
        bf16 h0 = __float2bfloat16(o0), h1 = __float2bfloat16(o1);
        bf16 h2 = __float2bfloat16(o2), h3 = __float2bfloat16(o3);
        *(uint32_t*)(g_cxh + i1) = ((uint32_t)*(uint16_t*)&h1 << 16) | *(uint16_t*)&h0;
        *(uint32_t*)(g_cxh + i2) = ((uint32_t)*(uint16_t*)&h3 << 16) | *(uint16_t*)&h2;
        *(uint32_t*)(g_cxl + i1) = pack_bf2(o0 - __bfloat162float(h0), o1 - __bfloat162float(h1));
        *(uint32_t*)(g_cxl + i2) = pack_bf2(o2 - __bfloat162float(h2), o3 - __bfloat162float(h3));
    }
}

// ---------------------------------------------------------------------------
extern "C" void kernel_launch(void* const* d_in, const int* in_sizes, int n_in,
                              void* d_out, int out_size)
{
    const float* x  = (const float*)d_in[0];
    const float* wq = (const float*)d_in[1];
    const float* wk = (const float*)d_in[2];
    const float* wv = (const float*)d_in[3];
    const float* wo = (const float*)d_in[4];
    const float* cs = (const float*)d_in[5];
    const float* sn = (const float*)d_in[6];
    float* out = (float*)d_out;

    bf16 *xh, *xl, *cxh, *cxl, *wqh, *wql, *wkh, *wkl, *wvh, *wvl, *woh, *wol;
    cudaGetSymbolAddress((void**)&xh,  g_xh);  cudaGetSymbolAddress((void**)&xl,  g_xl);
    cudaGetSymbolAddress((void**)&cxh, g_cxh); cudaGetSymbolAddress((void**)&cxl, g_cxl);
    cudaGetSymbolAddress((void**)&wqh, g_wqh); cudaGetSymbolAddress((void**)&wql, g_wql);
    cudaGetSymbolAddress((void**)&wkh, g_wkh); cudaGetSymbolAddress((void**)&wkl, g_wkl);
    cudaGetSymbolAddress((void**)&wvh, g_wvh); cudaGetSymbolAddress((void**)&wvl, g_wvl);
    cudaGetSymbolAddress((void**)&woh, g_woh); cudaGetSymbolAddress((void**)&wol, g_wol);

    // 1. one fused split-conversion launch (x as 2 z-slices + 4 weights)
    const int q4 = CONV_Z_ELEMS / 4;   // 1M float4 per z-slice
    convert_all<<<dim3((q4 + 255) / 256, 1, 6), 256>>>(
        (const float4*)x, (const float4*)wq, (const float4*)wk,
        (const float4*)wv, (const float4*)wo,
        (__nv_bfloat162*)xh, (__nv_bfloat162*)xl,
        (__nv_bfloat162*)wqh, (__nv_bfloat162*)wql,
        (__nv_bfloat162*)wkh, (__nv_bfloat162*)wkl,
        (__nv_bfloat162*)wvh, (__nv_bfloat162*)wvl,
        (__nv_bfloat162*)woh, (__nv_bfloat162*)wol);

    // 2. QKV projection (mma.sync, round-8 proven config)
    cudaFuncSetAttribute(gemm_tc<true>,  cudaFuncAttributeMaxDynamicSharedMemorySize, GEMM_SMEM);
    cudaFuncSetAttribute(gemm_tc<false>, cudaFuncAttributeMaxDynamicSharedMemorySize, GEMM_SMEM);
    gemm_tc<true><<<dim3(DM / 128, (Bb * Tt) / 128, 3), 256, GEMM_SMEM>>>(
        xh, xl, wqh, wql, wkh, wkl, wvh, wvl, nullptr);

    // 3. RoPE + split to bf16 (vectorized; q scaled by 1/sqrt(D))
    int nrope4 = Bb * Hh * Tt * (HALF / 4);
    rope_split<<<(nrope4 + 255) / 256, 256>>>(cs, sn, 1.0f / sqrtf((float)Dd));

    // 4. Flash attention (mma.sync) -> writes ctx splits directly
    cudaFuncSetAttribute(attn_mma, cudaFuncAttributeMaxDynamicSharedMemorySize, ATTN2_SMEM);
    attn_mma<<<dim3(Tt / 128, Bb * Hh), 256, ATTN2_SMEM>>>();

    // 5. output projection -> d_out
    gemm_tc<false><<<dim3(DM / 128, (Bb * Tt) / 128, 1), 256, GEMM_SMEM>>>(
        cxh, cxl, woh, wol, woh, wol, woh, wol, out);
}

// round 16
// speedup vs baseline: 1.1073x; 1.0025x over previous
#include <cuda_runtime.h>
#include <cuda_bf16.h>
#include <cstdint>
#include <math.h>

typedef __nv_bfloat16 bf16;

#define Bb   2
#define Tt   2048
#define DM   2048
#define Hh   16
#define Dd   128
#define HALF 64

// ---------------------------------------------------------------------------
// Device scratch (static — no runtime allocation allowed)
// ---------------------------------------------------------------------------
__device__ float g_q[(size_t)Bb * Hh * Tt * Dd];     // fp32 [b][h][t][d] (pre-rope)
__device__ float g_k[(size_t)Bb * Hh * Tt * Dd];
__device__ float g_v[(size_t)Bb * Hh * Tt * Dd];

// split-bf16 attention operands [b][h][t][d]
__device__ bf16 g_qh[(size_t)Bb * Hh * Tt * Dd], g_ql[(size_t)Bb * Hh * Tt * Dd];
__device__ bf16 g_kh[(size_t)Bb * Hh * Tt * Dd], g_kl[(size_t)Bb * Hh * Tt * Dd];
__device__ bf16 g_vh[(size_t)Bb * Hh * Tt * Dd], g_vl[(size_t)Bb * Hh * Tt * Dd];

// split-bf16 GEMM operands
__device__ bf16 g_xh[(size_t)Bb * Tt * DM];
__device__ bf16 g_xl[(size_t)Bb * Tt * DM];
__device__ bf16 g_cxh[(size_t)Bb * Tt * DM];   // ctx splits, written by attention
__device__ bf16 g_cxl[(size_t)Bb * Tt * DM];
__device__ bf16 g_wqh[(size_t)DM * DM], g_wql[(size_t)DM * DM];
__device__ bf16 g_wkh[(size_t)DM * DM], g_wkl[(size_t)DM * DM];
__device__ bf16 g_wvh[(size_t)DM * DM], g_wvl[(size_t)DM * DM];
__device__ bf16 g_woh[(size_t)DM * DM], g_wol[(size_t)DM * DM];

// ---------------------------------------------------------------------------
// PTX helpers (sm_80-class only — bench ptxas target is plain sm_103)
// ---------------------------------------------------------------------------
__device__ __forceinline__ uint32_t smem_u32(const void* p) {
    uint32_t a;
    asm("{ .reg .u64 t; cvta.to.shared.u64 t, %1; cvt.u32.u64 %0, t; }"
        : "=r"(a) : "l"(p));
    return a;
}
__device__ __forceinline__ void cp16(uint32_t dst, const void* src) {
    asm volatile("cp.async.cg.shared.global [%0], [%1], 16;" :: "r"(dst), "l"(src));
}
#define CP_COMMIT()   asm volatile("cp.async.commit_group;" ::: "memory")
#define CP_WAIT(n)    asm volatile("cp.async.wait_group %0;" :: "n"(n) : "memory")

__device__ __forceinline__ void ldsm4(uint32_t* r, uint32_t a) {
    asm volatile("ldmatrix.sync.aligned.m8n8.x4.shared.b16 {%0,%1,%2,%3}, [%4];"
                 : "=r"(r[0]), "=r"(r[1]), "=r"(r[2]), "=r"(r[3]) : "r"(a));
}
__device__ __forceinline__ void ldsm4t(uint32_t* r, uint32_t a) {
    asm volatile("ldmatrix.sync.aligned.m8n8.x4.trans.shared.b16 {%0,%1,%2,%3}, [%4];"
                 : "=r"(r[0]), "=r"(r[1]), "=r"(r[2]), "=r"(r[3]) : "r"(a));
}
__device__ __forceinline__ void ldsm2(uint32_t* r, uint32_t a) {
    asm volatile("ldmatrix.sync.aligned.m8n8.x2.shared.b16 {%0,%1}, [%2];"
                 : "=r"(r[0]), "=r"(r[1]) : "r"(a));
}
__device__ __forceinline__ void mma16816(float* c, const uint32_t* a, const uint32_t* b) {
    asm volatile(
        "mma.sync.aligned.m16n8k16.row.col.f32.bf16.bf16.f32 "
        "{%0,%1,%2,%3}, {%4,%5,%6,%7}, {%8,%9}, {%0,%1,%2,%3};"
        : "+f"(c[0]), "+f"(c[1]), "+f"(c[2]), "+f"(c[3])
        : "r"(a[0]), "r"(a[1]), "r"(a[2]), "r"(a[3]), "r"(b[0]), "r"(b[1]));
}
__device__ __forceinline__ uint32_t pack_bf2(float a, float b) {
    __nv_bfloat162 h = __floats2bfloat162_rn(a, b);
    return *(uint32_t*)&h;
}

// ---------------------------------------------------------------------------
// mma.sync split-bf16 GEMM (round-8 proven configuration, byte-identical):
// CTA 128x128, 256 threads, 64x32 warp tile, BK=64, 3-stage pipeline (192KB).
// Stage: [Ah 16K][Al 16K][Bh 16K][Bl 16K]. Rows 128B = 8 chunks, chunk ^= row&7.
// B via ldsm2; term-major MMA order.
// ---------------------------------------------------------------------------
#define NSTAGE 3
#define STAGE_BYTES 65536
#define GEMM_SMEM (NSTAGE * STAGE_BYTES)
#define NK (DM / 64)

__device__ __forceinline__ uint32_t sw_off(int row, int chunk) {
    return (uint32_t)(row * 128 + ((chunk ^ (row & 7)) * 16));
}

__device__ __forceinline__ void load_stage(uint32_t sbuf,
    const bf16* __restrict__ Ah, const bf16* __restrict__ Al,
    const bf16* __restrict__ Bh, const bf16* __restrict__ Bl,
    int m0, int n0, int k0, int tid)
{
    #pragma unroll
    for (int i = 0; i < 16; ++i) {
        int idx = tid + i * 256;          // 0..4095
        int tile = idx >> 10;             // 0..3  (Ah, Al, Bh, Bl)
        int rem  = idx & 1023;
        int r = rem >> 3, c = rem & 7;    // row 0..127, chunk 0..7
        uint32_t so = sw_off(r, c);
        const bf16* src = (tile == 0) ? Ah : (tile == 1) ? Al
                        : (tile == 2) ? Bh : Bl;
        int rg = (tile < 2) ? (m0 + r) : (n0 + r);
        cp16(sbuf + tile * 16384 + so,
             (const char*)src + ((size_t)rg * DM + k0 + c * 8) * 2);
    }
}

__device__ __forceinline__ void compute_stage(uint32_t sbuf,
    float acc[4][4][4], int wm, int wn, int lane)
{
    const int arow = lane & 15;
    const int achk = lane >> 4;          // 0 or 1
    const int brow = lane & 7;
    const int bchk = (lane >> 3) & 1;
    #pragma unroll
    for (int ks = 0; ks < 4; ++ks) {
        uint32_t ah[4][4], al[4][4], bh[4][2], bl[4][2];
        #pragma unroll
        for (int mt = 0; mt < 4; ++mt) {
            int r = wm * 64 + mt * 16 + arow;
            uint32_t ad = sbuf + sw_off(r, ks * 2 + achk);
            ldsm4(ah[mt], ad);
            ldsm4(al[mt], ad + 16384);
        }
        #pragma unroll
        for (int nt = 0; nt < 4; ++nt) {
            int r = wn * 32 + nt * 8 + brow;
            uint32_t bd = sbuf + 32768 + sw_off(r, ks * 2 + bchk);
            ldsm2(bh[nt], bd);
            ldsm2(bl[nt], bd + 16384);
        }
        // term-major: all 16 accs visited before any acc repeats
        #pragma unroll
        for (int mt = 0; mt < 4; ++mt)
            #pragma unroll
            for (int nt = 0; nt < 4; ++nt)
                mma16816(acc[mt][nt], ah[mt], bh[nt]);
        #pragma unroll
        for (int mt = 0; mt < 4; ++mt)
            #pragma unroll
            for (int nt = 0; nt < 4; ++nt)
                mma16816(acc[mt][nt], ah[mt], bl[nt]);
        #pragma unroll
        for (int mt = 0; mt < 4; ++mt)
            #pragma unroll
            for (int nt = 0; nt < 4; ++nt)
                mma16816(acc[mt][nt], al[mt], bh[nt]);
    }
}

template<bool QKV>
__global__ void __launch_bounds__(256, 1) gemm_tc(
    const bf16* __restrict__ Ah,  const bf16* __restrict__ Al,
    const bf16* __restrict__ Bh0, const bf16* __restrict__ Bl0,
    const bf16* __restrict__ Bh1, const bf16* __restrict__ Bl1,
    const bf16* __restrict__ Bh2, const bf16* __restrict__ Bl2,
    float* __restrict__ outp)
{
    extern __shared__ char smp[];
    const int tid  = threadIdx.x;
    const int wid  = tid >> 5;
    const int lane = tid & 31;
    const int wm   = wid >> 2;
    const int wn   = wid & 3;
    const int m0 = blockIdx.y * 128;
    const int n0 = blockIdx.x * 128;

    const bf16* Bh = Bh0;
    const bf16* Bl = Bl0;
    float* out = outp;
    if (QKV) {
        if (blockIdx.z == 1)      { Bh = Bh1; Bl = Bl1; out = g_k; }
        else if (blockIdx.z == 2) { Bh = Bh2; Bl = Bl2; out = g_v; }
        else                      { out = g_q; }
    }

    const uint32_t sbase = smem_u32(smp);

    float acc[4][4][4];
    #pragma unroll
    for (int a = 0; a < 4; ++a)
        #pragma unroll
        for (int b = 0; b < 4; ++b)
            #pragma unroll
            for (int c = 0; c < 4; ++c) acc[a][b][c] = 0.0f;

    // prologue: fill 2 stages
    load_stage(sbase, Ah, Al, Bh, Bl, m0, n0, 0, tid);
    CP_COMMIT();
    load_stage(sbase + STAGE_BYTES, Ah, Al, Bh, Bl, m0, n0, 64, tid);
    CP_COMMIT();

    uint32_t bufs[3] = {sbase, sbase + STAGE_BYTES, sbase + 2 * STAGE_BYTES};
    for (int kt = 0; kt < NK; ++kt) {
        CP_WAIT(1);
        __syncthreads();
        if (kt + 2 < NK) {
            load_stage(bufs[(kt + 2) % 3], Ah, Al, Bh, Bl, m0, n0, (kt + 2) * 64, tid);
            CP_COMMIT();
        }
        compute_stage(bufs[kt % 3], acc, wm, wn, lane);
    }

    const int lr = lane >> 2;
    const int lc = (lane & 3) * 2;
    #pragma unroll
    for (int mt = 0; mt < 4; ++mt) {
        #pragma unroll
        for (int nt = 0; nt < 4; ++nt) {
            int mA = m0 + wm * 64 + mt * 16 + lr;
            int col = n0 + wn * 32 + nt * 8 + lc;
            float2 v0 = make_float2(acc[mt][nt][0], acc[mt][nt][1]);
            float2 v1 = make_float2(acc[mt][nt][2], acc[mt][nt][3]);
            if (QKV) {
                const int h = col >> 7, d = col & 127;
                int b = mA >> 11, t = mA & (Tt - 1);
                *(float2*)(out + (((size_t)b * Hh + h) * Tt + t) * Dd + d) = v0;
                int mB = mA + 8;
                b = mB >> 11; t = mB & (Tt - 1);
                *(float2*)(out + (((size_t)b * Hh + h) * Tt + t) * Dd + d) = v1;
            } else {
                *(float2*)(out + (size_t)mA * DM + col) = v0;
                *(float2*)(out + (size_t)(mA + 8) * DM + col) = v1;
            }
        }
    }
}

// ---------------------------------------------------------------------------
// fp32 -> (hi, lo) bf16 split — single launch for x (2 halves) + 4 weights
// ---------------------------------------------------------------------------
#define CONV_Z_ELEMS (DM * DM)   // 4M elements per z-slice
__global__ void convert_all(
    const float4* __restrict__ x,
    const float4* __restrict__ wq, const float4* __restrict__ wk,
    const float4* __restrict__ wv, const float4* __restrict__ wo,
    __nv_bfloat162* __restrict__ xh, __nv_bfloat162* __restrict__ xl,
    __nv_bfloat162* __restrict__ wqh, __nv_bfloat162* __restrict__ wql,
    __nv_bfloat162* __restrict__ wkh, __nv_bfloat162* __restrict__ wkl,
    __nv_bfloat162* __restrict__ wvh, __nv_bfloat162* __restrict__ wvl,
    __nv_bfloat162* __restrict__ woh, __nv_bfloat162* __restrict__ wol)
{
    const int z = blockIdx.z;
    const int q4 = CONV_Z_ELEMS / 4;  // float4s per z-slice
    const float4* src;
    __nv_bfloat162 *hi, *lo;
    switch (z) {
        case 0: src = x;           hi = xh;            lo = xl;            break;
        case 1: src = x + q4;      hi = xh + q4 * 2;   lo = xl + q4 * 2;   break;
        case 2: src = wq;          hi = wqh;           lo = wql;           break;
        case 3: src = wk;          hi = wkh;           lo = wkl;           break;
        case 4: src = wv;          hi = wvh;           lo = wvl;           break;
        default: src = wo;         hi = woh;           lo = wol;           break;
    }
    int i = blockIdx.x * blockDim.x + threadIdx.x;
    if (i >= q4) return;
    float4 f = src[i];
    bf16 h0 = __float2bfloat16(f.x), h1 = __float2bfloat16(f.y);
    bf16 h2 = __float2bfloat16(f.z), h3 = __float2bfloat16(f.w);
    hi[2 * i]     = __halves2bfloat162(h0, h1);
    hi[2 * i + 1] = __halves2bfloat162(h2, h3);
    *(uint32_t*)&lo[2 * i]     = pack_bf2(f.x - __bfloat162float(h0), f.y - __bfloat162float(h1));
    *(uint32_t*)&lo[2 * i + 1] = pack_bf2(f.z - __bfloat162float(h2), f.w - __bfloat162float(h3));
}

// ---------------------------------------------------------------------------
// RoPE + split to bf16, vectorized (proven round-15).
// q gets log2(e)/sqrt(D) folded in -> attention softmax uses bare exp2f.
// ---------------------------------------------------------------------------
__global__ void rope_split(const float* __restrict__ cos_t,
                           const float* __restrict__ sin_t, float qscale)
{
    int idx = blockIdx.x * blockDim.x + threadIdx.x;   // 0 .. B*H*T*16 - 1
    if (idx >= Bb * Hh * Tt * (HALF / 4)) return;
    int dp4 = (idx & 15) * 4;          // 0,4,...,60
    int row = idx >> 4;                // (b*H + h)*T + t
    int t   = row & (Tt - 1);
    size_t base = (size_t)row * Dd;

    float4 c4 = *(const float4*)(cos_t + t * HALF + dp4);
    float4 s4 = *(const float4*)(sin_t + t * HALF + dp4);
    float4 q1 = *(const float4*)(g_q + base + dp4);
    float4 q2 = *(const float4*)(g_q + base + dp4 + HALF);
    float4 k1 = *(const float4*)(g_k + base + dp4);
    float4 k2 = *(const float4*)(g_k + base + dp4 + HALF);
    float4 v1 = *(const float4*)(g_v + base + dp4);
    float4 v2 = *(const float4*)(g_v + base + dp4 + HALF);

    float qo1[4] = {(q1.x * c4.x - q2.x * s4.x) * qscale,
                    (q1.y * c4.y - q2.y * s4.y) * qscale,
                    (q1.z * c4.z - q2.z * s4.z) * qscale,
                    (q1.w * c4.w - q2.w * s4.w) * qscale};
    float qo2[4] = {(q1.x * s4.x + q2.x * c4.x) * qscale,
                    (q1.y * s4.y + q2.y * c4.y) * qscale,
                    (q1.z * s4.z + q2.z * c4.z) * qscale,
                    (q1.w * s4.w + q2.w * c4.w) * qscale};
    float ko1[4] = {k1.x * c4.x - k2.x * s4.x, k1.y * c4.y - k2.y * s4.y,
                    k1.z * c4.z - k2.z * s4.z, k1.w * c4.w - k2.w * s4.w};
    float ko2[4] = {k1.x * s4.x + k2.x * c4.x, k1.y * s4.y + k2.y * c4.y,
                    k1.z * s4.z + k2.z * c4.z, k1.w * s4.w + k2.w * c4.w};
    float vo1[4] = {v1.x, v1.y, v1.z, v1.w};
    float vo2[4] = {v2.x, v2.y, v2.z, v2.w};

    #pragma unroll
    for (int g = 0; g < 2; ++g) {
        float* qsel = g ? qo2 : qo1;
        float* ksel = g ? ko2 : ko1;
        float* vsel = g ? vo2 : vo1;
        size_t off = base + dp4 + g * HALF;
        #pragma unroll
        for (int p = 0; p < 2; ++p) {
            float a = qsel[2 * p], b = qsel[2 * p + 1];
            bf16 ha = __float2bfloat16(a), hb = __float2bfloat16(b);
            *(uint32_t*)(g_qh + off + 2 * p) = ((uint32_t)*(uint16_t*)&hb << 16) | *(uint16_t*)&ha;
            *(uint32_t*)(g_ql + off + 2 * p) = pack_bf2(a - __bfloat162float(ha), b - __bfloat162float(hb));

            a = ksel[2 * p]; b = ksel[2 * p + 1];
            ha = __float2bfloat16(a); hb = __float2bfloat16(b);
            *(uint32_t*)(g_kh + off + 2 * p) = ((uint32_t)*(uint16_t*)&hb << 16) | *(uint16_t*)&ha;
            *(uint32_t*)(g_kl + off + 2 * p) = pack_bf2(a - __bfloat162float(ha), b - __bfloat162float(hb));

            a = vsel[2 * p]; b = vsel[2 * p + 1];
            ha = __float2bfloat16(a); hb = __float2bfloat16(b);
            *(uint32_t*)(g_vh + off + 2 * p) = ((uint32_t)*(uint16_t*)&hb << 16) | *(uint16_t*)&ha;
            *(uint32_t*)(g_vl + off + 2 * p) = pack_bf2(a - __bfloat162float(ha), b - __bfloat162float(hb));
        }
    }
}

// ---------------------------------------------------------------------------
// Flash attention on mma.sync, split-bf16, causal.
// S is in log2 domain (log2e folded into q) -> softmax uses bare exp2f
// (single MUFU.EX2, no FMUL on the softmax critical path).
// BQ=128 q-rows/CTA (8 warps x 16 rows), BKT=64 KV per step.
// SMEM: [Qh 32K][Ql 32K] + 2 stages x [Kh 16K][Kl 16K][Vh 16K][Vl 16K] = 192K.
// ---------------------------------------------------------------------------
#define ATTN2_SMEM 196608

__device__ __forceinline__ uint32_t aoff(int row, int chunk) {
    return (uint32_t)(row * 256 + ((chunk ^ (row & 7)) * 16));
}

__device__ __forceinline__ void attn_load_stage(uint32_t sb, int bhT, int k0, int tid)
{
    #pragma unroll
    for (int t8 = 0; t8 < 16; ++t8) {
        int i = tid + t8 * 256;
        int tile = i >> 10;
        int rem = i & 1023;
        int row = rem >> 4, chunk = rem & 15;
        const bf16* src = (tile == 0) ? g_kh : (tile == 1) ? g_kl
                        : (tile == 2) ? g_vh : g_vl;
        cp16(sb + tile * 16384 + aoff(row, chunk),
             src + (((size_t)(bhT + k0 + row)) << 7) + chunk * 8);
    }
}

__global__ void __launch_bounds__(256, 1) attn_mma()
{
    extern __shared__ char smp[];
    const uint32_t sb = smem_u32(smp);
    const int tid  = threadIdx.x;
    const int wid  = tid >> 5;
    const int lane = tid & 31;
    const int bh   = blockIdx.y;
    const int qi   = gridDim.x - 1 - blockIdx.x;   // heavy tiles first
    const int q0   = qi * 128;
    const int bhT  = bh * Tt;
    const int wrow = wid * 16;

    // Load Q tile (qh, ql): 128 rows x 256B each
    #pragma unroll
    for (int t8 = 0; t8 < 16; ++t8) {
        int i = tid + t8 * 256;
        int tile = i >> 11;
        int rem = i & 2047;
        int row = rem >> 4, chunk = rem & 15;
        const bf16* src = tile ? g_ql : g_qh;
        cp16(sb + tile * 32768 + aoff(row, chunk),
             src + (((size_t)(bhT + q0 + row)) << 7) + chunk * 8);
    }
    attn_load_stage(sb + 65536, bhT, 0, tid);
    CP_COMMIT();

    float m1 = -1e30f, m2 = -1e30f, l1 = 0.0f, l2 = 0.0f;
    float O[16][4];
    #pragma unroll
    for (int i = 0; i < 16; ++i)
        #pragma unroll
        for (int j = 0; j < 4; ++j) O[i][j] = 0.0f;

    const int nsteps = 2 * qi + 2;
    for (int s = 0; s < nsteps; ++s) {
        if (s + 1 < nsteps) {
            attn_load_stage(sb + 65536 + ((s + 1) & 1) * 65536, bhT, (s + 1) * 64, tid);
            CP_COMMIT();
            CP_WAIT(1);
        } else {
            CP_WAIT(0);
        }
        __syncthreads();
        const uint32_t stg = sb + 65536 + (s & 1) * 65536;

        // ---- S = Q K^T (3-term split, fp32 acc, log2-domain pre-scaled) ----
        float sa[8][4];
        #pragma unroll
        for (int i = 0; i < 8; ++i)
            #pragma unroll
            for (int j = 0; j < 4; ++j) sa[i][j] = 0.0f;

        const int arow = wrow + (lane & 15);
        #pragma unroll
        for (int ks = 0; ks < 8; ++ks) {
            uint32_t ah[4], al[4];
            uint32_t ad = sb + aoff(arow, ks * 2 + (lane >> 4));
            ldsm4(ah, ad);
            ldsm4(al, ad + 32768);
            #pragma unroll
            for (int ntp = 0; ntp < 4; ++ntp) {
                int brow = ntp * 16 + (lane & 7) + (lane >> 4) * 8;
                int bchk = ks * 2 + ((lane >> 3) & 1);
                uint32_t kbh[4], kbl[4];
                uint32_t bd = stg + aoff(brow, bchk);
                ldsm4(kbh, bd);
                ldsm4(kbl, bd + 16384);
                mma16816(sa[2 * ntp],     ah, kbh);
                mma16816(sa[2 * ntp + 1], ah, kbh + 2);
                mma16816(sa[2 * ntp],     ah, kbl);
                mma16816(sa[2 * ntp + 1], ah, kbl + 2);
                mma16816(sa[2 * ntp],     al, kbh);
                mma16816(sa[2 * ntp + 1], al, kbh + 2);
            }
        }

        // ---- causal mask (diagonal steps only) ----
        const int k0 = s * 64;
        const int gr1 = q0 + wrow + (lane >> 2);
        const int gr2 = gr1 + 8;
        if (s >= 2 * qi) {
            #pragma unroll
            for (int nt = 0; nt < 8; ++nt) {
                int c = k0 + nt * 8 + (lane & 3) * 2;
                if (c     > gr1) sa[nt][0] = -1e30f;
                if (c + 1 > gr1) sa[nt][1] = -1e30f;
                if (c     > gr2) sa[nt][2] = -1e30f;
                if (c + 1 > gr2) sa[nt][3] = -1e30f;
            }
        }

        // ---- online softmax in log2 domain (rows fully intra-warp) ----
        float mx1 = -1e30f, mx2 = -1e30f;
        #pragma unroll
        for (int nt = 0; nt < 8; ++nt) {
            mx1 = fmaxf(mx1, fmaxf(sa[nt][0], sa[nt][1]));
            mx2 = fmaxf(mx2, fmaxf(sa[nt][2], sa[nt][3]));
        }
        mx1 = fmaxf(mx1, __shfl_xor_sync(0xffffffff, mx1, 1));
        mx1 = fmaxf(mx1, __shfl_xor_sync(0xffffffff, mx1, 2));
        mx2 = fmaxf(mx2, __shfl_xor_sync(0xffffffff, mx2, 1));
        mx2 = fmaxf(mx2, __shfl_xor_sync(0xffffffff, mx2, 2));
        float mn1 = fmaxf(m1, mx1), mn2 = fmaxf(m2, mx2);
        float al1 = exp2f(m1 - mn1), al2 = exp2f(m2 - mn2);
        m1 = mn1; m2 = mn2;

        float rs1 = 0.0f, rs2 = 0.0f;
        uint32_t pa_h[8], pa_l[8], pb_h[8], pb_l[8];
        #pragma unroll
        for (int nt = 0; nt < 8; ++nt) {
            float p0 = exp2f(sa[nt][0] - mn1);
            float p1 = exp2f(sa[nt][1] - mn1);
            float p2 = exp2f(sa[nt][2] - mn2);
            float p3 = exp2f(sa[nt][3] - mn2);
            rs1 += p0 + p1;
            rs2 += p2 + p3;
            bf16 h0 = __float2bfloat16(p0), h1 = __float2bfloat16(p1);
            bf16 h2 = __float2bfloat16(p2), h3 = __float2bfloat16(p3);
            pa_h[nt] = ((uint32_t)*(uint16_t*)&h1 << 16) | *(uint16_t*)&h0;
            pb_h[nt] = ((uint32_t)*(uint16_t*)&h3 << 16) | *(uint16_t*)&h2;
            pa_l[nt] = pack_bf2(p0 - __bfloat162float(h0), p1 - __bfloat162float(h1));
            pb_l[nt] = pack_bf2(p2 - __bfloat162float(h2), p3 - __bfloat162float(h3));
        }
        rs1 += __shfl_xor_sync(0xffffffff, rs1, 1);
        rs1 += __shfl_xor_sync(0xffffffff, rs1, 2);
        rs2 += __shfl_xor_sync(0xffffffff, rs2, 1);
        rs2 += __shfl_xor_sync(0xffffffff, rs2, 2);
        l1 = l1 * al1 + rs1;
        l2 = l2 * al2 + rs2;

        #pragma unroll
        for (int nt = 0; nt < 16; ++nt) {
            O[nt][0] *= al1; O[nt][1] *= al1;
            O[nt][2] *= al2; O[nt][3] *= al2;
        }

        // ---- O += P V (3-term split; V via ldmatrix.trans) ----
        #pragma unroll
        for (int kt = 0; kt < 4; ++kt) {
            uint32_t A_h[4] = {pa_h[2 * kt], pb_h[2 * kt], pa_h[2 * kt + 1], pb_h[2 * kt + 1]};
            uint32_t A_l[4] = {pa_l[2 * kt], pb_l[2 * kt], pa_l[2 * kt + 1], pb_l[2 * kt + 1]};
            int vrow = kt * 16 + (lane & 7) + ((lane >> 3) & 1) * 8;
            #pragma unroll
            for (int g = 0; g < 8; ++g) {
                int vchk = g * 2 + (lane >> 4);
                uint32_t vbh[4], vbl[4];
                uint32_t vd = stg + 32768 + aoff(vrow, vchk);
                ldsm4t(vbh, vd);
                ldsm4t(vbl, vd + 16384);
                mma16816(O[2 * g],     A_h, vbh);
                mma16816(O[2 * g + 1], A_h, vbh + 2);
                mma16816(O[2 * g],     A_h, vbl);
                mma16816(O[2 * g + 1], A_h, vbl + 2);
                mma16816(O[2 * g],     A_l, vbh);
                mma16816(O[2 * g + 1], A_l, vbh + 2);
            }
        }
        __syncthreads();
    }

    // ---- epilogue: normalize, split to bf16, write ctx splits ----
    const float inv1 = 1.0f / l1, inv2 = 1.0f / l2;
    const int b = bh >> 4, h = bh & 15;
    const int r1 = q0 + wrow + (lane >> 2);
    #pragma unroll
    for (int nt = 0; nt < 16; ++nt) {
        int col = h * Dd + nt * 8 + (lane & 3) * 2;
        size_t i1 = ((size_t)(b * Tt + r1)) * DM + col;
        size_t i2 = i1 + 8 * DM;
        float o0 = O[nt][0] * inv1, o1 = O[nt][1] * inv1;
        float o2 = O[nt][2] * inv2, o3 = O[nt][3] * inv2;
        bf16 h0 = __float2bfloat16(o0), h1 = __float2bfloat16(o1);
        bf16 h2 = __float2bfloat16(o2), h3 = __float2bfloat16(o3);
        *(uint32_t*)(g_cxh + i1) = ((uint32_t)*(uint16_t*)&h1 << 16) | *(uint16_t*)&h0;
        *(uint32_t*)(g_cxh + i2) = ((uint32_t)*(uint16_t*)&h3 << 16) | *(uint16_t*)&h2;
        *(uint32_t*)(g_cxl + i1) = pack_bf2(o0 - __bfloat162float(h0), o1 - __bfloat162float(h1));
        *(uint32_t*)(g_cxl + i2) = pack_bf2(o2 - __bfloat162float(h2), o3 - __bfloat162float(h3));
    }
}

// ---------------------------------------------------------------------------
extern "C" void kernel_launch(void* const* d_in, const int* in_sizes, int n_in,
                              void* d_out, int out_size)
{
    const float* x  = (const float*)d_in[0];
    const float* wq = (const float*)d_in[1];
    const float* wk = (const float*)d_in[2];
    const float* wv = (const float*)d_in[3];
    const float* wo = (const float*)d_in[4];
    const float* cs = (const float*)d_in[5];
    const float* sn = (const float*)d_in[6];
    float* out = (float*)d_out;

    bf16 *xh, *xl, *cxh, *cxl, *wqh, *wql, *wkh, *wkl, *wvh, *wvl, *woh, *wol;
    cudaGetSymbolAddress((void**)&xh,  g_xh);  cudaGetSymbolAddress((void**)&xl,  g_xl);
    cudaGetSymbolAddress((void**)&cxh, g_cxh); cudaGetSymbolAddress((void**)&cxl, g_cxl);
    cudaGetSymbolAddress((void**)&wqh, g_wqh); cudaGetSymbolAddress((void**)&wql, g_wql);
    cudaGetSymbolAddress((void**)&wkh, g_wkh); cudaGetSymbolAddress((void**)&wkl, g_wkl);
    cudaGetSymbolAddress((void**)&wvh, g_wvh); cudaGetSymbolAddress((void**)&wvl, g_wvl);
    cudaGetSymbolAddress((void**)&woh, g_woh); cudaGetSymbolAddress((void**)&wol, g_wol);

    // 1. one fused split-conversion launch (x as 2 z-slices + 4 weights)
    const int q4 = CONV_Z_ELEMS / 4;   // 1M float4 per z-slice
    convert_all<<<dim3((q4 + 255) / 256, 1, 6), 256>>>(
        (const float4*)x, (const float4*)wq, (const float4*)wk,
        (const float4*)wv, (const float4*)wo,
        (__nv_bfloat162*)xh, (__nv_bfloat162*)xl,
        (__nv_bfloat162*)wqh, (__nv_bfloat162*)wql,
        (__nv_bfloat162*)wkh, (__nv_bfloat162*)wkl,
        (__nv_bfloat162*)wvh, (__nv_bfloat162*)wvl,
        (__nv_bfloat162*)woh, (__nv_bfloat162*)wol);

    // 2. QKV projection (mma.sync, round-8 proven config)
    cudaFuncSetAttribute(gemm_tc<true>,  cudaFuncAttributeMaxDynamicSharedMemorySize, GEMM_SMEM);
    cudaFuncSetAttribute(gemm_tc<false>, cudaFuncAttributeMaxDynamicSharedMemorySize, GEMM_SMEM);
    gemm_tc<true><<<dim3(DM / 128, (Bb * Tt) / 128, 3), 256, GEMM_SMEM>>>(
        xh, xl, wqh, wql, wkh, wkl, wvh, wvl, nullptr);

    // 3. RoPE + split to bf16 (vectorized; q scaled by log2(e)/sqrt(D))
    int nrope4 = Bb * Hh * Tt * (HALF / 4);
    rope_split<<<(nrope4 + 255) / 256, 256>>>(cs, sn,
        1.4426950408889634f / sqrtf((float)Dd));

    // 4. Flash attention (mma.sync, exp2 softmax) -> writes ctx splits directly
    cudaFuncSetAttribute(attn_mma, cudaFuncAttributeMaxDynamicSharedMemorySize, ATTN2_SMEM);
    attn_mma<<<dim3(Tt / 128, Bb * Hh), 256, ATTN2_SMEM>>>();

    // 5. output projection -> d_out
    gemm_tc<false><<<dim3(DM / 128, (Bb * Tt) / 128, 1), 256, GEMM_SMEM>>>(
        cxh, cxl, woh, wol, woh, wol, woh, wol, out);
}

// round 17
// speedup vs baseline: 1.1192x; 1.0107x over previous
#include <cuda_runtime.h>
#include <cuda_bf16.h>
#include <cstdint>
#include <math.h>

typedef __nv_bfloat16 bf16;

#define Bb   2
#define Tt   2048
#define DM   2048
#define Hh   16
#define Dd   128
#define HALF 64

// ---------------------------------------------------------------------------
// Device scratch (static — no runtime allocation allowed)
// ---------------------------------------------------------------------------
__device__ float g_q[(size_t)Bb * Hh * Tt * Dd];     // fp32 [b][h][t][d] (pre-rope)
__device__ float g_k[(size_t)Bb * Hh * Tt * Dd];
__device__ float g_v[(size_t)Bb * Hh * Tt * Dd];

// split-bf16 attention operands [b][h][t][d]
__device__ bf16 g_qh[(size_t)Bb * Hh * Tt * Dd], g_ql[(size_t)Bb * Hh * Tt * Dd];
__device__ bf16 g_kh[(size_t)Bb * Hh * Tt * Dd], g_kl[(size_t)Bb * Hh * Tt * Dd];
__device__ bf16 g_vh[(size_t)Bb * Hh * Tt * Dd], g_vl[(size_t)Bb * Hh * Tt * Dd];

// split-bf16 GEMM operands
__device__ bf16 g_xh[(size_t)Bb * Tt * DM];
__device__ bf16 g_xl[(size_t)Bb * Tt * DM];
__device__ bf16 g_cxh[(size_t)Bb * Tt * DM];   // ctx splits, written by attention
__device__ bf16 g_cxl[(size_t)Bb * Tt * DM];
__device__ bf16 g_wqh[(size_t)DM * DM], g_wql[(size_t)DM * DM];
__device__ bf16 g_wkh[(size_t)DM * DM], g_wkl[(size_t)DM * DM];
__device__ bf16 g_wvh[(size_t)DM * DM], g_wvl[(size_t)DM * DM];
__device__ bf16 g_woh[(size_t)DM * DM], g_wol[(size_t)DM * DM];

// ---------------------------------------------------------------------------
// PTX helpers (sm_80-class only — bench ptxas target is plain sm_103)
// ---------------------------------------------------------------------------
__device__ __forceinline__ uint32_t smem_u32(const void* p) {
    uint32_t a;
    asm("{ .reg .u64 t; cvta.to.shared.u64 t, %1; cvt.u32.u64 %0, t; }"
        : "=r"(a) : "l"(p));
    return a;
}
__device__ __forceinline__ void cp16(uint32_t dst, const void* src) {
    asm volatile("cp.async.cg.shared.global [%0], [%1], 16;" :: "r"(dst), "l"(src));
}
#define CP_COMMIT()   asm volatile("cp.async.commit_group;" ::: "memory")
#define CP_WAIT(n)    asm volatile("cp.async.wait_group %0;" :: "n"(n) : "memory")

__device__ __forceinline__ void ldsm4(uint32_t* r, uint32_t a) {
    asm volatile("ldmatrix.sync.aligned.m8n8.x4.shared.b16 {%0,%1,%2,%3}, [%4];"
                 : "=r"(r[0]), "=r"(r[1]), "=r"(r[2]), "=r"(r[3]) : "r"(a));
}
__device__ __forceinline__ void ldsm4t(uint32_t* r, uint32_t a) {
    asm volatile("ldmatrix.sync.aligned.m8n8.x4.trans.shared.b16 {%0,%1,%2,%3}, [%4];"
                 : "=r"(r[0]), "=r"(r[1]), "=r"(r[2]), "=r"(r[3]) : "r"(a));
}
__device__ __forceinline__ void ldsm2(uint32_t* r, uint32_t a) {
    asm volatile("ldmatrix.sync.aligned.m8n8.x2.shared.b16 {%0,%1}, [%2];"
                 : "=r"(r[0]), "=r"(r[1]) : "r"(a));
}
__device__ __forceinline__ void mma16816(float* c, const uint32_t* a, const uint32_t* b) {
    asm volatile(
        "mma.sync.aligned.m16n8k16.row.col.f32.bf16.bf16.f32 "
        "{%0,%1,%2,%3}, {%4,%5,%6,%7}, {%8,%9}, {%0,%1,%2,%3};"
        : "+f"(c[0]), "+f"(c[1]), "+f"(c[2]), "+f"(c[3])
        : "r"(a[0]), "r"(a[1]), "r"(a[2]), "r"(a[3]), "r"(b[0]), "r"(b[1]));
}
__device__ __forceinline__ uint32_t pack_bf2(float a, float b) {
    __nv_bfloat162 h = __floats2bfloat162_rn(a, b);
    return *(uint32_t*)&h;
}

// ---------------------------------------------------------------------------
// mma.sync split-bf16 GEMM (round-8 proven configuration, byte-identical):
// CTA 128x128, 256 threads, 64x32 warp tile, BK=64, 3-stage pipeline (192KB).
// ---------------------------------------------------------------------------
#define NSTAGE 3
#define STAGE_BYTES 65536
#define GEMM_SMEM (NSTAGE * STAGE_BYTES)
#define NK (DM / 64)

__device__ __forceinline__ uint32_t sw_off(int row, int chunk) {
    return (uint32_t)(row * 128 + ((chunk ^ (row & 7)) * 16));
}

__device__ __forceinline__ void load_stage(uint32_t sbuf,
    const bf16* __restrict__ Ah, const bf16* __restrict__ Al,
    const bf16* __restrict__ Bh, const bf16* __restrict__ Bl,
    int m0, int n0, int k0, int tid)
{
    #pragma unroll
    for (int i = 0; i < 16; ++i) {
        int idx = tid + i * 256;          // 0..4095
        int tile = idx >> 10;             // 0..3  (Ah, Al, Bh, Bl)
        int rem  = idx & 1023;
        int r = rem >> 3, c = rem & 7;    // row 0..127, chunk 0..7
        uint32_t so = sw_off(r, c);
        const bf16* src = (tile == 0) ? Ah : (tile == 1) ? Al
                        : (tile == 2) ? Bh : Bl;
        int rg = (tile < 2) ? (m0 + r) : (n0 + r);
        cp16(sbuf + tile * 16384 + so,
             (const char*)src + ((size_t)rg * DM + k0 + c * 8) * 2);
    }
}

__device__ __forceinline__ void compute_stage(uint32_t sbuf,
    float acc[4][4][4], int wm, int wn, int lane)
{
    const int arow = lane & 15;
    const int achk = lane >> 4;          // 0 or 1
    const int brow = lane & 7;
    const int bchk = (lane >> 3) & 1;
    #pragma unroll
    for (int ks = 0; ks < 4; ++ks) {
        uint32_t ah[4][4], al[4][4], bh[4][2], bl[4][2];
        #pragma unroll
        for (int mt = 0; mt < 4; ++mt) {
            int r = wm * 64 + mt * 16 + arow;
            uint32_t ad = sbuf + sw_off(r, ks * 2 + achk);
            ldsm4(ah[mt], ad);
            ldsm4(al[mt], ad + 16384);
        }
        #pragma unroll
        for (int nt = 0; nt < 4; ++nt) {
            int r = wn * 32 + nt * 8 + brow;
            uint32_t bd = sbuf + 32768 + sw_off(r, ks * 2 + bchk);
            ldsm2(bh[nt], bd);
            ldsm2(bl[nt], bd + 16384);
        }
        // term-major: all 16 accs visited before any acc repeats
        #pragma unroll
        for (int mt = 0; mt < 4; ++mt)
            #pragma unroll
            for (int nt = 0; nt < 4; ++nt)
                mma16816(acc[mt][nt], ah[mt], bh[nt]);
        #pragma unroll
        for (int mt = 0; mt < 4; ++mt)
            #pragma unroll
            for (int nt = 0; nt < 4; ++nt)
                mma16816(acc[mt][nt], ah[mt], bl[nt]);
        #pragma unroll
        for (int mt = 0; mt < 4; ++mt)
            #pragma unroll
            for (int nt = 0; nt < 4; ++nt)
                mma16816(acc[mt][nt], al[mt], bh[nt]);
    }
}

template<bool QKV>
__global__ void __launch_bounds__(256, 1) gemm_tc(
    const bf16* __restrict__ Ah,  const bf16* __restrict__ Al,
    const bf16* __restrict__ Bh0, const bf16* __restrict__ Bl0,
    const bf16* __restrict__ Bh1, const bf16* __restrict__ Bl1,
    const bf16* __restrict__ Bh2, const bf16* __restrict__ Bl2,
    float* __restrict__ outp)
{
    extern __shared__ char smp[];
    const int tid  = threadIdx.x;
    const int wid  = tid >> 5;
    const int lane = tid & 31;
    const int wm   = wid >> 2;
    const int wn   = wid & 3;
    const int m0 = blockIdx.y * 128;
    const int n0 = blockIdx.x * 128;

    const bf16* Bh = Bh0;
    const bf16* Bl = Bl0;
    float* out = outp;
    if (QKV) {
        if (blockIdx.z == 1)      { Bh = Bh1; Bl = Bl1; out = g_k; }
        else if (blockIdx.z == 2) { Bh = Bh2; Bl = Bl2; out = g_v; }
        else                      { out = g_q; }
    }

    const uint32_t sbase = smem_u32(smp);

    float acc[4][4][4];
    #pragma unroll
    for (int a = 0; a < 4; ++a)
        #pragma unroll
        for (int b = 0; b < 4; ++b)
            #pragma unroll
            for (int c = 0; c < 4; ++c) acc[a][b][c] = 0.0f;

    // prologue: fill 2 stages
    load_stage(sbase, Ah, Al, Bh, Bl, m0, n0, 0, tid);
    CP_COMMIT();
    load_stage(sbase + STAGE_BYTES, Ah, Al, Bh, Bl, m0, n0, 64, tid);
    CP_COMMIT();

    uint32_t bufs[3] = {sbase, sbase + STAGE_BYTES, sbase + 2 * STAGE_BYTES};
    for (int kt = 0; kt < NK; ++kt) {
        CP_WAIT(1);
        __syncthreads();
        if (kt + 2 < NK) {
            load_stage(bufs[(kt + 2) % 3], Ah, Al, Bh, Bl, m0, n0, (kt + 2) * 64, tid);
            CP_COMMIT();
        }
        compute_stage(bufs[kt % 3], acc, wm, wn, lane);
    }

    const int lr = lane >> 2;
    const int lc = (lane & 3) * 2;
    #pragma unroll
    for (int mt = 0; mt < 4; ++mt) {
        #pragma unroll
        for (int nt = 0; nt < 4; ++nt) {
            int mA = m0 + wm * 64 + mt * 16 + lr;
            int col = n0 + wn * 32 + nt * 8 + lc;
            float2 v0 = make_float2(acc[mt][nt][0], acc[mt][nt][1]);
            float2 v1 = make_float2(acc[mt][nt][2], acc[mt][nt][3]);
            if (QKV) {
                const int h = col >> 7, d = col & 127;
                int b = mA >> 11, t = mA & (Tt - 1);
                *(float2*)(out + (((size_t)b * Hh + h) * Tt + t) * Dd + d) = v0;
                int mB = mA + 8;
                b = mB >> 11; t = mB & (Tt - 1);
                *(float2*)(out + (((size_t)b * Hh + h) * Tt + t) * Dd + d) = v1;
            } else {
                *(float2*)(out + (size_t)mA * DM + col) = v0;
                *(float2*)(out + (size_t)(mA + 8) * DM + col) = v1;
            }
        }
    }
}

// ---------------------------------------------------------------------------
// fp32 -> (hi, lo) bf16 split — single launch for x (2 halves) + 4 weights
// ---------------------------------------------------------------------------
#define CONV_Z_ELEMS (DM * DM)   // 4M elements per z-slice
__global__ void convert_all(
    const float4* __restrict__ x,
    const float4* __restrict__ wq, const float4* __restrict__ wk,
    const float4* __restrict__ wv, const float4* __restrict__ wo,
    __nv_bfloat162* __restrict__ xh, __nv_bfloat162* __restrict__ xl,
    __nv_bfloat162* __restrict__ wqh, __nv_bfloat162* __restrict__ wql,
    __nv_bfloat162* __restrict__ wkh, __nv_bfloat162* __restrict__ wkl,
    __nv_bfloat162* __restrict__ wvh, __nv_bfloat162* __restrict__ wvl,
    __nv_bfloat162* __restrict__ woh, __nv_bfloat162* __restrict__ wol)
{
    const int z = blockIdx.z;
    const int q4 = CONV_Z_ELEMS / 4;  // float4s per z-slice
    const float4* src;
    __nv_bfloat162 *hi, *lo;
    switch (z) {
        case 0: src = x;           hi = xh;            lo = xl;            break;
        case 1: src = x + q4;      hi = xh + q4 * 2;   lo = xl + q4 * 2;   break;
        case 2: src = wq;          hi = wqh;           lo = wql;           break;
        case 3: src = wk;          hi = wkh;           lo = wkl;           break;
        case 4: src = wv;          hi = wvh;           lo = wvl;           break;
        default: src = wo;         hi = woh;           lo = wol;           break;
    }
    int i = blockIdx.x * blockDim.x + threadIdx.x;
    if (i >= q4) return;
    float4 f = src[i];
    bf16 h0 = __float2bfloat16(f.x), h1 = __float2bfloat16(f.y);
    bf16 h2 = __float2bfloat16(f.z), h3 = __float2bfloat16(f.w);
    hi[2 * i]     = __halves2bfloat162(h0, h1);
    hi[2 * i + 1] = __halves2bfloat162(h2, h3);
    *(uint32_t*)&lo[2 * i]     = pack_bf2(f.x - __bfloat162float(h0), f.y - __bfloat162float(h1));
    *(uint32_t*)&lo[2 * i + 1] = pack_bf2(f.z - __bfloat162float(h2), f.w - __bfloat162float(h3));
}

// ---------------------------------------------------------------------------
// RoPE + split to bf16, vectorized (proven round-15).
// q gets log2(e)/sqrt(D) folded in -> attention softmax uses bare exp2f.
// ---------------------------------------------------------------------------
__global__ void rope_split(const float* __restrict__ cos_t,
                           const float* __restrict__ sin_t, float qscale)
{
    int idx = blockIdx.x * blockDim.x + threadIdx.x;   // 0 .. B*H*T*16 - 1
    if (idx >= Bb * Hh * Tt * (HALF / 4)) return;
    int dp4 = (idx & 15) * 4;          // 0,4,...,60
    int row = idx >> 4;                // (b*H + h)*T + t
    int t   = row & (Tt - 1);
    size_t base = (size_t)row * Dd;

    float4 c4 = *(const float4*)(cos_t + t * HALF + dp4);
    float4 s4 = *(const float4*)(sin_t + t * HALF + dp4);
    float4 q1 = *(const float4*)(g_q + base + dp4);
    float4 q2 = *(const float4*)(g_q + base + dp4 + HALF);
    float4 k1 = *(const float4*)(g_k + base + dp4);
    float4 k2 = *(const float4*)(g_k + base + dp4 + HALF);
    float4 v1 = *(const float4*)(g_v + base + dp4);
    float4 v2 = *(const float4*)(g_v + base + dp4 + HALF);

    float qo1[4] = {(q1.x * c4.x - q2.x * s4.x) * qscale,
                    (q1.y * c4.y - q2.y * s4.y) * qscale,
                    (q1.z * c4.z - q2.z * s4.z) * qscale,
                    (q1.w * c4.w - q2.w * s4.w) * qscale};
    float qo2[4] = {(q1.x * s4.x + q2.x * c4.x) * qscale,
                    (q1.y * s4.y + q2.y * c4.y) * qscale,
                    (q1.z * s4.z + q2.z * c4.z) * qscale,
                    (q1.w * s4.w + q2.w * c4.w) * qscale};
    float ko1[4] = {k1.x * c4.x - k2.x * s4.x, k1.y * c4.y - k2.y * s4.y,
                    k1.z * c4.z - k2.z * s4.z, k1.w * c4.w - k2.w * s4.w};
    float ko2[4] = {k1.x * s4.x + k2.x * c4.x, k1.y * s4.y + k2.y * c4.y,
                    k1.z * s4.z + k2.z * c4.z, k1.w * s4.w + k2.w * c4.w};
    float vo1[4] = {v1.x, v1.y, v1.z, v1.w};
    float vo2[4] = {v2.x, v2.y, v2.z, v2.w};

    #pragma unroll
    for (int g = 0; g < 2; ++g) {
        float* qsel = g ? qo2 : qo1;
        float* ksel = g ? ko2 : ko1;
        float* vsel = g ? vo2 : vo1;
        size_t off = base + dp4 + g * HALF;
        #pragma unroll
        for (int p = 0; p < 2; ++p) {
            float a = qsel[2 * p], b = qsel[2 * p + 1];
            bf16 ha = __float2bfloat16(a), hb = __float2bfloat16(b);
            *(uint32_t*)(g_qh + off + 2 * p) = ((uint32_t)*(uint16_t*)&hb << 16) | *(uint16_t*)&ha;
            *(uint32_t*)(g_ql + off + 2 * p) = pack_bf2(a - __bfloat162float(ha), b - __bfloat162float(hb));

            a = ksel[2 * p]; b = ksel[2 * p + 1];
            ha = __float2bfloat16(a); hb = __float2bfloat16(b);
            *(uint32_t*)(g_kh + off + 2 * p) = ((uint32_t)*(uint16_t*)&hb << 16) | *(uint16_t*)&ha;
            *(uint32_t*)(g_kl + off + 2 * p) = pack_bf2(a - __bfloat162float(ha), b - __bfloat162float(hb));

            a = vsel[2 * p]; b = vsel[2 * p + 1];
            ha = __float2bfloat16(a); hb = __float2bfloat16(b);
            *(uint32_t*)(g_vh + off + 2 * p) = ((uint32_t)*(uint16_t*)&hb << 16) | *(uint16_t*)&ha;
            *(uint32_t*)(g_vl + off + 2 * p) = pack_bf2(a - __bfloat162float(ha), b - __bfloat162float(hb));
        }
    }
}

// ---------------------------------------------------------------------------
// Flash attention on mma.sync, split-bf16, causal, exp2 softmax.
// NEW: BQ=64 q-rows/CTA (4 warps x 16 rows), BKT=32 KV per step, 128 threads.
// SMEM: [Qh 16K][Ql 16K] + 2 stages x [Kh 8K][Kl 8K][Vh 8K][Vl 8K] = 96K
// -> 2 CTAs/SM (occupancy 12.5% -> 25%), CTA-level latency hiding.
// Same proven pipeline/fragment/MMA pattern scaled down.
// ---------------------------------------------------------------------------
#define ATTN2_SMEM 98304
#define AQ_BYTES   16384   // one Q split tile: 64 rows x 256B
#define AKV_STAGE  32768   // one KV stage: 4 tiles x 32 rows x 256B

__device__ __forceinline__ uint32_t aoff(int row, int chunk) {
    return (uint32_t)(row * 256 + ((chunk ^ (row & 7)) * 16));
}

__device__ __forceinline__ void attn_load_stage(uint32_t sb, int bhT, int k0, int tid)
{
    #pragma unroll
    for (int t8 = 0; t8 < 16; ++t8) {
        int i = tid + t8 * 128;           // 0..2047
        int tile = i >> 9;                // 0..3 (kh, kl, vh, vl); 512 items each
        int rem = i & 511;
        int row = rem >> 4, chunk = rem & 15;   // row 0..31
        const bf16* src = (tile == 0) ? g_kh : (tile == 1) ? g_kl
                        : (tile == 2) ? g_vh : g_vl;
        cp16(sb + tile * 8192 + aoff(row, chunk),
             src + (((size_t)(bhT + k0 + row)) << 7) + chunk * 8);
    }
}

__global__ void __launch_bounds__(128, 2) attn_mma()
{
    extern __shared__ char smp[];
    const uint32_t sb = smem_u32(smp);
    const int tid  = threadIdx.x;
    const int wid  = tid >> 5;        // 0..3
    const int lane = tid & 31;
    const int bh   = blockIdx.y;
    const int qi   = gridDim.x - 1 - blockIdx.x;   // heavy tiles first
    const int q0   = qi * 64;
    const int bhT  = bh * Tt;
    const int wrow = wid * 16;

    // Load Q tile (qh, ql): 64 rows x 256B each
    #pragma unroll
    for (int t8 = 0; t8 < 16; ++t8) {
        int i = tid + t8 * 128;           // 0..2047
        int tile = i >> 10;               // 0=qh 1=ql (1024 items each)
        int rem = i & 1023;
        int row = rem >> 4, chunk = rem & 15;   // row 0..63
        const bf16* src = tile ? g_ql : g_qh;
        cp16(sb + tile * AQ_BYTES + aoff(row, chunk),
             src + (((size_t)(bhT + q0 + row)) << 7) + chunk * 8);
    }
    attn_load_stage(sb + 2 * AQ_BYTES, bhT, 0, tid);
    CP_COMMIT();

    float m1 = -1e30f, m2 = -1e30f, l1 = 0.0f, l2 = 0.0f;
    float O[16][4];
    #pragma unroll
    for (int i = 0; i < 16; ++i)
        #pragma unroll
        for (int j = 0; j < 4; ++j) O[i][j] = 0.0f;

    const int nsteps = 2 * qi + 2;     // (q0 + 64) / 32
    for (int s = 0; s < nsteps; ++s) {
        if (s + 1 < nsteps) {
            attn_load_stage(sb + 2 * AQ_BYTES + ((s + 1) & 1) * AKV_STAGE,
                            bhT, (s + 1) * 32, tid);
            CP_COMMIT();
            CP_WAIT(1);
        } else {
            CP_WAIT(0);
        }
        __syncthreads();
        const uint32_t stg = sb + 2 * AQ_BYTES + (s & 1) * AKV_STAGE;

        // ---- S = Q K^T (3-term split, fp32 acc, log2-domain pre-scaled) ----
        float sa[4][4];
        #pragma unroll
        for (int i = 0; i < 4; ++i)
            #pragma unroll
            for (int j = 0; j < 4; ++j) sa[i][j] = 0.0f;

        const int arow = wrow + (lane & 15);
        #pragma unroll
        for (int ks = 0; ks < 8; ++ks) {
            uint32_t ah[4], al[4];
            uint32_t ad = sb + aoff(arow, ks * 2 + (lane >> 4));
            ldsm4(ah, ad);
            ldsm4(al, ad + AQ_BYTES);
            #pragma unroll
            for (int ntp = 0; ntp < 2; ++ntp) {
                int brow = ntp * 16 + (lane & 7) + (lane >> 4) * 8;  // 0..31
                int bchk = ks * 2 + ((lane >> 3) & 1);
                uint32_t kbh[4], kbl[4];
                uint32_t bd = stg + aoff(brow, bchk);
                ldsm4(kbh, bd);
                ldsm4(kbl, bd + 8192);
                mma16816(sa[2 * ntp],     ah, kbh);
                mma16816(sa[2 * ntp + 1], ah, kbh + 2);
                mma16816(sa[2 * ntp],     ah, kbl);
                mma16816(sa[2 * ntp + 1], ah, kbl + 2);
                mma16816(sa[2 * ntp],     al, kbh);
                mma16816(sa[2 * ntp + 1], al, kbh + 2);
            }
        }

        // ---- causal mask (diagonal steps only: last 2) ----
        const int k0 = s * 32;
        const int gr1 = q0 + wrow + (lane >> 2);
        const int gr2 = gr1 + 8;
        if (s >= 2 * qi) {
            #pragma unroll
            for (int nt = 0; nt < 4; ++nt) {
                int c = k0 + nt * 8 + (lane & 3) * 2;
                if (c     > gr1) sa[nt][0] = -1e30f;
                if (c + 1 > gr1) sa[nt][1] = -1e30f;
                if (c     > gr2) sa[nt][2] = -1e30f;
                if (c + 1 > gr2) sa[nt][3] = -1e30f;
            }
        }

        // ---- online softmax in log2 domain (rows fully intra-warp) ----
        float mx1 = -1e30f, mx2 = -1e30f;
        #pragma unroll
        for (int nt = 0; nt < 4; ++nt) {
            mx1 = fmaxf(mx1, fmaxf(sa[nt][0], sa[nt][1]));
            mx2 = fmaxf(mx2, fmaxf(sa[nt][2], sa[nt][3]));
        }
        mx1 = fmaxf(mx1, __shfl_xor_sync(0xffffffff, mx1, 1));
        mx1 = fmaxf(mx1, __shfl_xor_sync(0xffffffff, mx1, 2));
        mx2 = fmaxf(mx2, __shfl_xor_sync(0xffffffff, mx2, 1));
        mx2 = fmaxf(mx2, __shfl_xor_sync(0xffffffff, mx2, 2));
        float mn1 = fmaxf(m1, mx1), mn2 = fmaxf(m2, mx2);
        float al1 = exp2f(m1 - mn1), al2 = exp2f(m2 - mn2);
        m1 = mn1; m2 = mn2;

        float rs1 = 0.0f, rs2 = 0.0f;
        uint32_t pa_h[4], pa_l[4], pb_h[4], pb_l[4];
        #pragma unroll
        for (int nt = 0; nt < 4; ++nt) {
            float p0 = exp2f(sa[nt][0] - mn1);
            float p1 = exp2f(sa[nt][1] - mn1);
            float p2 = exp2f(sa[nt][2] - mn2);
            float p3 = exp2f(sa[nt][3] - mn2);
            rs1 += p0 + p1;
            rs2 += p2 + p3;
            bf16 h0 = __float2bfloat16(p0), h1 = __float2bfloat16(p1);
            bf16 h2 = __float2bfloat16(p2), h3 = __float2bfloat16(p3);
            pa_h[nt] = ((uint32_t)*(uint16_t*)&h1 << 16) | *(uint16_t*)&h0;
            pb_h[nt] = ((uint32_t)*(uint16_t*)&h3 << 16) | *(uint16_t*)&h2;
            pa_l[nt] = pack_bf2(p0 - __bfloat162float(h0), p1 - __bfloat162float(h1));
            pb_l[nt] = pack_bf2(p2 - __bfloat162float(h2), p3 - __bfloat162float(h3));
        }
        rs1 += __shfl_xor_sync(0xffffffff, rs1, 1);
        rs1 += __shfl_xor_sync(0xffffffff, rs1, 2);
        rs2 += __shfl_xor_sync(0xffffffff, rs2, 1);
        rs2 += __shfl_xor_sync(0xffffffff, rs2, 2);
        l1 = l1 * al1 + rs1;
        l2 = l2 * al2 + rs2;

        #pragma unroll
        for (int nt = 0; nt < 16; ++nt) {
            O[nt][0] *= al1; O[nt][1] *= al1;
            O[nt][2] *= al2; O[nt][3] *= al2;
        }

        // ---- O += P V (3-term split; V via ldmatrix.trans) ----
        #pragma unroll
        for (int kt = 0; kt < 2; ++kt) {
            uint32_t A_h[4] = {pa_h[2 * kt], pb_h[2 * kt], pa_h[2 * kt + 1], pb_h[2 * kt + 1]};
            uint32_t A_l[4] = {pa_l[2 * kt], pb_l[2 * kt], pa_l[2 * kt + 1], pb_l[2 * kt + 1]};
            int vrow = kt * 16 + (lane & 7) + ((lane >> 3) & 1) * 8;   // 0..31
            #pragma unroll
            for (int g = 0; g < 8; ++g) {
                int vchk = g * 2 + (lane >> 4);
                uint32_t vbh[4], vbl[4];
                uint32_t vd = stg + 16384 + aoff(vrow, vchk);
                ldsm4t(vbh, vd);
                ldsm4t(vbl, vd + 8192);
                mma16816(O[2 * g],     A_h, vbh);
                mma16816(O[2 * g + 1], A_h, vbh + 2);
                mma16816(O[2 * g],     A_h, vbl);
                mma16816(O[2 * g + 1], A_h, vbl + 2);
                mma16816(O[2 * g],     A_l, vbh);
                mma16816(O[2 * g + 1], A_l, vbh + 2);
            }
        }
        __syncthreads();
    }

    // ---- epilogue: normalize, split to bf16, write ctx splits ----
    const float inv1 = 1.0f / l1, inv2 = 1.0f / l2;
    const int b = bh >> 4, h = bh & 15;
    const int r1 = q0 + wrow + (lane >> 2);
    #pragma unroll
    for (int nt = 0; nt < 16; ++nt) {
        int col = h * Dd + nt * 8 + (lane & 3) * 2;
        size_t i1 = ((size_t)(b * Tt + r1)) * DM + col;
        size_t i2 = i1 + 8 * DM;
        float o0 = O[nt][0] * inv1, o1 = O[nt][1] * inv1;
        float o2 = O[nt][2] * inv2, o3 = O[nt][3] * inv2;
        bf16 h0 = __float2bfloat16(o0), h1 = __float2bfloat16(o1);
        bf16 h2 = __float2bfloat16(o2), h3 = __float2bfloat16(o3);
        *(uint32_t*)(g_cxh + i1) = ((uint32_t)*(uint16_t*)&h1 << 16) | *(uint16_t*)&h0;
        *(uint32_t*)(g_cxh + i2) = ((uint32_t)*(uint16_t*)&h3 << 16) | *(uint16_t*)&h2;
        *(uint32_t*)(g_cxl + i1) = pack_bf2(o0 - __bfloat162float(h0), o1 - __bfloat162float(h1));
        *(uint32_t*)(g_cxl + i2) = pack_bf2(o2 - __bfloat162float(h2), o3 - __bfloat162float(h3));
    }
}

// ---------------------------------------------------------------------------
extern "C" void kernel_launch(void* const* d_in, const int* in_sizes, int n_in,
                              void* d_out, int out_size)
{
    const float* x  = (const float*)d_in[0];
    const float* wq = (const float*)d_in[1];
    const float* wk = (const float*)d_in[2];
    const float* wv = (const float*)d_in[3];
    const float* wo = (const float*)d_in[4];
    const float* cs = (const float*)d_in[5];
    const float* sn = (const float*)d_in[6];
    float* out = (float*)d_out;

    bf16 *xh, *xl, *cxh, *cxl, *wqh, *wql, *wkh, *wkl, *wvh, *wvl, *woh, *wol;
    cudaGetSymbolAddress((void**)&xh,  g_xh);  cudaGetSymbolAddress((void**)&xl,  g_xl);
    cudaGetSymbolAddress((void**)&cxh, g_cxh); cudaGetSymbolAddress((void**)&cxl, g_cxl);
    cudaGetSymbolAddress((void**)&wqh, g_wqh); cudaGetSymbolAddress((void**)&wql, g_wql);
    cudaGetSymbolAddress((void**)&wkh, g_wkh); cudaGetSymbolAddress((void**)&wkl, g_wkl);
    cudaGetSymbolAddress((void**)&wvh, g_wvh); cudaGetSymbolAddress((void**)&wvl, g_wvl);
    cudaGetSymbolAddress((void**)&woh, g_woh); cudaGetSymbolAddress((void**)&wol, g_wol);

    // 1. one fused split-conversion launch (x as 2 z-slices + 4 weights)
    const int q4 = CONV_Z_ELEMS / 4;   // 1M float4 per z-slice
    convert_all<<<dim3((q4 + 255) / 256, 1, 6), 256>>>(
        (const float4*)x, (const float4*)wq, (const float4*)wk,
        (const float4*)wv, (const float4*)wo,
        (__nv_bfloat162*)xh, (__nv_bfloat162*)xl,
        (__nv_bfloat162*)wqh, (__nv_bfloat162*)wql,
        (__nv_bfloat162*)wkh, (__nv_bfloat162*)wkl,
        (__nv_bfloat162*)wvh, (__nv_bfloat162*)wvl,
        (__nv_bfloat162*)woh, (__nv_bfloat162*)wol);

    // 2. QKV projection (mma.sync, round-8 proven config)
    cudaFuncSetAttribute(gemm_tc<true>,  cudaFuncAttributeMaxDynamicSharedMemorySize, GEMM_SMEM);
    cudaFuncSetAttribute(gemm_tc<false>, cudaFuncAttributeMaxDynamicSharedMemorySize, GEMM_SMEM);
    gemm_tc<true><<<dim3(DM / 128, (Bb * Tt) / 128, 3), 256, GEMM_SMEM>>>(
        xh, xl, wqh, wql, wkh, wkl, wvh, wvl, nullptr);

    // 3. RoPE + split to bf16 (vectorized; q scaled by log2(e)/sqrt(D))
    int nrope4 = Bb * Hh * Tt * (HALF / 4);
    rope_split<<<(nrope4 + 255) / 256, 256>>>(cs, sn,
        1.4426950408889634f / sqrtf((float)Dd));

    // 4. Flash attention (mma.sync, BQ=64/BKT=32, 2 CTAs/SM) -> ctx splits
    cudaFuncSetAttribute(attn_mma, cudaFuncAttributeMaxDynamicSharedMemorySize, ATTN2_SMEM);
    attn_mma<<<dim3(Tt / 64, Bb * Hh), 128, ATTN2_SMEM>>>();

    // 5. output projection -> d_out
    gemm_tc<false><<<dim3(DM / 128, (Bb * Tt) / 128, 1), 256, GEMM_SMEM>>>(
        cxh, cxl, woh, wol, woh, wol, woh, wol, out);
}